// round 2
// baseline (speedup 1.0000x reference)
#include <cuda_runtime.h>

#define DD 192
#define LL 1024
#define BT 128
#define NS 8
#define ROWS_BIG (BT*LL)   /* 131072 */
#define ROWS_S   (BT*NS)   /* 1024   */

// ---------------- scratch (device globals; no allocs allowed) ----------------
__device__ float g_xln [ROWS_BIG * DD];    // ln(features)
__device__ float g_kvb [ROWS_BIG * 384];   // k | v interleaved per row
__device__ float g_qb  [ROWS_S * DD];
__device__ float g_s0  [ROWS_S * DD];
__device__ float g_t1  [ROWS_S * DD];
__device__ float g_t2  [ROWS_S * DD];
__device__ float g_qkvb[ROWS_S * 576];
__device__ float g_hid [ROWS_S * 512];

// ---------------- LayerNorm: one warp per row of 192 ----------------
__global__ void ln_kernel(const float* __restrict__ x, float* __restrict__ y,
                          const float* __restrict__ g, const float* __restrict__ b,
                          int rows) {
  int w = (blockIdx.x * blockDim.x + threadIdx.x) >> 5;
  int lane = threadIdx.x & 31;
  if (w >= rows) return;
  const float* xr = x + (size_t)w * DD;
  float v[6]; float s = 0.f, s2 = 0.f;
#pragma unroll
  for (int j = 0; j < 6; j++) { float t = xr[j*32 + lane]; v[j]=t; s+=t; s2+=t*t; }
#pragma unroll
  for (int o = 16; o; o >>= 1) {
    s  += __shfl_xor_sync(0xffffffffu, s,  o);
    s2 += __shfl_xor_sync(0xffffffffu, s2, o);
  }
  float m = s * (1.f/DD);
  float inv = rsqrtf(fmaxf(s2*(1.f/DD) - m*m, 0.f) + 1e-5f);
  float* yr = y + (size_t)w * DD;
#pragma unroll
  for (int j = 0; j < 6; j++) { int d = j*32+lane; yr[d] = (v[j]-m)*inv*g[d] + b[d]; }
}

// ---------------- packed f32x2 helpers (sm_100+ FFMA2) ----------------
__device__ __forceinline__ unsigned long long dup2(float x) {
  unsigned long long r;
  asm("mov.b64 %0, {%1, %1};" : "=l"(r) : "f"(x));
  return r;
}
__device__ __forceinline__ void ffma2(unsigned long long& d, unsigned long long a, unsigned long long b) {
  asm("fma.rn.f32x2 %0, %1, %2, %0;" : "+l"(d) : "l"(a), "l"(b));
}

// ---------------- generic GEMM: C(M x N) = alpha*A(M x K) @ W(N x K)^T [+bias][relu][+res]
// tiles: 128(M) x 64(N) x 16(K), 256 threads, 8x4 micro-tile via FFMA2 pairs.
// All M are multiples of 128, all N of 64, all K of 16 in this problem.
#define GBM 128
#define GBN 64
#define GBK 16

__global__ __launch_bounds__(256)
void gemm_kernel(const float* __restrict__ A, const float* __restrict__ W,
                 const float* __restrict__ bias, const float* __restrict__ res,
                 float* __restrict__ C, int M, int Ncols, int K, int ldc,
                 float alpha, int relu) {
  __shared__ __align__(16) float As[GBK][GBM+4];
  __shared__ __align__(16) float Ws[GBK][GBN+4];
  int t  = threadIdx.x;
  int m0 = blockIdx.x * GBM;
  int n0 = blockIdx.y * GBN;
  int lr = t >> 2;            // 0..63
  int lc = (t & 3) << 2;      // 0,4,8,12
  const float* Ap0 = A + (size_t)(m0 + lr)      * K + lc;
  const float* Ap1 = A + (size_t)(m0 + lr + 64) * K + lc;
  const float* Wp  = W + (size_t)(n0 + lr)      * K + lc;
  int ty = t >> 4, tx = t & 15;
  unsigned long long acc[4][4] = {};  // 4 row-pairs x 4 cols, packed f32x2

  for (int k0 = 0; k0 < K; k0 += GBK) {
    float4 a0 = *(const float4*)(Ap0 + k0);
    float4 a1 = *(const float4*)(Ap1 + k0);
    float4 w0 = *(const float4*)(Wp  + k0);
    __syncthreads();
    As[lc+0][lr]    = a0.x; As[lc+1][lr]    = a0.y; As[lc+2][lr]    = a0.z; As[lc+3][lr]    = a0.w;
    As[lc+0][lr+64] = a1.x; As[lc+1][lr+64] = a1.y; As[lc+2][lr+64] = a1.z; As[lc+3][lr+64] = a1.w;
    Ws[lc+0][lr]    = w0.x; Ws[lc+1][lr]    = w0.y; Ws[lc+2][lr]    = w0.z; Ws[lc+3][lr]    = w0.w;
    __syncthreads();
#pragma unroll
    for (int k = 0; k < GBK; k++) {
      const ulonglong2* ap = (const ulonglong2*)&As[k][ty*8];
      ulonglong2 p0 = ap[0];  // rows +0,+1 | +2,+3
      ulonglong2 p1 = ap[1];  // rows +4,+5 | +6,+7
      float4 wv = *(const float4*)&Ws[k][tx*4];
      unsigned long long wd0 = dup2(wv.x), wd1 = dup2(wv.y), wd2 = dup2(wv.z), wd3 = dup2(wv.w);
      ffma2(acc[0][0], p0.x, wd0); ffma2(acc[0][1], p0.x, wd1); ffma2(acc[0][2], p0.x, wd2); ffma2(acc[0][3], p0.x, wd3);
      ffma2(acc[1][0], p0.y, wd0); ffma2(acc[1][1], p0.y, wd1); ffma2(acc[1][2], p0.y, wd2); ffma2(acc[1][3], p0.y, wd3);
      ffma2(acc[2][0], p1.x, wd0); ffma2(acc[2][1], p1.x, wd1); ffma2(acc[2][2], p1.x, wd2); ffma2(acc[2][3], p1.x, wd3);
      ffma2(acc[3][0], p1.y, wd0); ffma2(acc[3][1], p1.y, wd1); ffma2(acc[3][2], p1.y, wd2); ffma2(acc[3][3], p1.y, wd3);
    }
  }
#pragma unroll
  for (int ip = 0; ip < 4; ip++) {
#pragma unroll
    for (int j = 0; j < 4; j++) {
      float lo, hi;
      asm("mov.b64 {%0, %1}, %2;" : "=f"(lo), "=f"(hi) : "l"(acc[ip][j]));
      int n = n0 + tx*4 + j;
      int m = m0 + ty*8 + ip*2;
      float bv = bias ? bias[n] : 0.f;
      float v0 = lo*alpha + bv;
      float v1 = hi*alpha + bv;
      if (relu) { v0 = fmaxf(v0, 0.f); v1 = fmaxf(v1, 0.f); }
      if (res)  { v0 += res[(size_t)m*Ncols + n]; v1 += res[(size_t)(m+1)*Ncols + n]; }
      C[(size_t)m*ldc + n]     = v0;
      C[(size_t)(m+1)*ldc + n] = v1;
    }
  }
}

// ---------------- inverse cross-attention (one block per bt) ----------------
// scores[n][s] = q[n]·k[s]; softmax over n (8 slots) per key s; then
// out[n] = (sum_s w[n][s] v[s]) / (sum_s w[n][s])   <- key renormalization
__global__ __launch_bounds__(256)
void invattn_kernel(const float* __restrict__ q, const float* __restrict__ kv,
                    float* __restrict__ out) {
  __shared__ float qs[NS][DD];
  __shared__ float sc[NS][LL];   // 32 KB
  __shared__ float den[NS];
  int bt = blockIdx.x;
  int t  = threadIdx.x;
  for (int i = t; i < NS*DD; i += 256) qs[i/DD][i%DD] = q[(size_t)bt*NS*DD + i];
  if (t < NS) den[t] = 0.f;
  __syncthreads();

  int warp = t >> 5, lane = t & 31;
  const float* kvb = kv + (size_t)bt * LL * 384;
  for (int s = warp; s < LL; s += 8) {
    const float* kr = kvb + (size_t)s * 384;
    float kk[6];
#pragma unroll
    for (int j = 0; j < 6; j++) kk[j] = kr[j*32 + lane];
#pragma unroll
    for (int n = 0; n < NS; n++) {
      float p = 0.f;
#pragma unroll
      for (int j = 0; j < 6; j++) p += kk[j] * qs[n][j*32 + lane];
#pragma unroll
      for (int o = 16; o; o >>= 1) p += __shfl_xor_sync(0xffffffffu, p, o);
      if (lane == 0) sc[n][s] = p;
    }
  }
  __syncthreads();

  float pd[NS] = {};
  for (int s = t; s < LL; s += 256) {
    float vN[NS]; float mx = -1e30f;
#pragma unroll
    for (int n = 0; n < NS; n++) { vN[n] = sc[n][s]; mx = fmaxf(mx, vN[n]); }
    float sum = 0.f;
#pragma unroll
    for (int n = 0; n < NS; n++) { vN[n] = __expf(vN[n] - mx); sum += vN[n]; }
    float r = 1.f / sum;
#pragma unroll
    for (int n = 0; n < NS; n++) { float wv = vN[n]*r; sc[n][s] = wv; pd[n] += wv; }
  }
#pragma unroll
  for (int n = 0; n < NS; n++) atomicAdd(&den[n], pd[n]);
  __syncthreads();

  if (t < DD) {
    float acc[NS] = {};
    const float* vb = kvb + 192 + t;
#pragma unroll 4
    for (int s = 0; s < LL; s++) {
      float vv = vb[(size_t)s * 384];
#pragma unroll
      for (int n = 0; n < NS; n++) acc[n] += sc[n][s] * vv;
    }
#pragma unroll
    for (int n = 0; n < NS; n++)
      out[((size_t)bt*NS + n)*DD + t] = acc[n] / den[n];
  }
}

// ---------------- standard MHA core: one block per (batch,head); nh=4, hd=48
// qkv: (S*Bb, 576) row (s*Bb+b); out: (S*Bb, 192)
__global__ __launch_bounds__(256)
void mha_kernel(const float* __restrict__ qkv, float* __restrict__ out, int S, int Bb) {
  extern __shared__ __align__(16) float smbuf[];
  int b = blockIdx.x >> 2, h = blockIdx.x & 3;
  float* qs = smbuf;
  float* ks = qs + S*48;
  float* vs = ks + S*48;
  float* sc = vs + S*48;     // QC x S
  int t = threadIdx.x;
  for (int i = t; i < S*48; i += 256) {
    int s = i / 48, e = i - s*48;
    size_t ro = ((size_t)s*Bb + b)*576 + h*48 + e;
    qs[i] = qkv[ro]; ks[i] = qkv[ro + 192]; vs[i] = qkv[ro + 384];
  }
  __syncthreads();
  const float scale = 0.14433756729740643f;  // 1/sqrt(48)
  const int QC = 64;
  for (int i0 = 0; i0 < S; i0 += QC) {
    for (int idx = t; idx < QC*S; idx += 256) {
      int i = idx / S, s = idx - i*S;
      const float4* qr = (const float4*)(qs + (i0+i)*48);
      const float4* kr = (const float4*)(ks + s*48);
      float p = 0.f;
#pragma unroll
      for (int j = 0; j < 12; j++) {
        float4 a = qr[j]; float4 kx = kr[j];
        p += a.x*kx.x + a.y*kx.y + a.z*kx.z + a.w*kx.w;
      }
      sc[idx] = p * scale;
    }
    __syncthreads();
    int warp = t >> 5, lane = t & 31;
    for (int i = warp; i < QC; i += 8) {
      float mx = -1e30f;
      for (int s = lane; s < S; s += 32) mx = fmaxf(mx, sc[i*S+s]);
#pragma unroll
      for (int o = 16; o; o >>= 1) mx = fmaxf(mx, __shfl_xor_sync(0xffffffffu, mx, o));
      float sum = 0.f;
      for (int s = lane; s < S; s += 32) { float e = __expf(sc[i*S+s]-mx); sc[i*S+s]=e; sum += e; }
#pragma unroll
      for (int o = 16; o; o >>= 1) sum += __shfl_xor_sync(0xffffffffu, sum, o);
      float r = 1.f / sum;
      for (int s = lane; s < S; s += 32) sc[i*S+s] *= r;
    }
    __syncthreads();
    for (int idx = t; idx < QC*48; idx += 256) {
      int i = idx / 48, e = idx - i*48;
      float acc = 0.f;
#pragma unroll 4
      for (int s = 0; s < S; s++) acc += sc[i*S+s] * vs[s*48+e];
      out[((size_t)(i0+i)*Bb + b)*192 + h*48 + e] = acc;
    }
    __syncthreads();
  }
}

// ---------------- (B,T,N,D) -> (B,N,T,D) ----------------
__global__ void transpose_kernel(const float* __restrict__ in, float* __restrict__ out) {
  int idx = blockIdx.x * 256 + threadIdx.x;
  if (idx >= ROWS_S * DD) return;
  int d = idx % DD; int r = idx / DD;
  int n = r & 7; int tt = (r >> 3) & 15; int bb = r >> 7;
  out[(((size_t)bb*8 + n)*16 + tt)*DD + d] = in[idx];
}

// ---------------- launcher ----------------
extern "C" void kernel_launch(void* const* d_in, const int* in_sizes, int n_in,
                              void* d_out, int out_size) {
  const float* features   = (const float*)d_in[0];
  const float* prev_slots = (const float*)d_in[1];
  const float* lnq_g  = (const float*)d_in[2],  *lnq_b  = (const float*)d_in[3];
  const float* lnkv_g = (const float*)d_in[4],  *lnkv_b = (const float*)d_in[5];
  const float* wq = (const float*)d_in[6],  *wk = (const float*)d_in[7];
  const float* wvw= (const float*)d_in[8],  *wo = (const float*)d_in[9];
  const float* lnt_g  = (const float*)d_in[10], *lnt_b  = (const float*)d_in[11];
  const float* t_in_w = (const float*)d_in[12], *t_in_b = (const float*)d_in[13];
  const float* t_out_w= (const float*)d_in[14], *t_out_b= (const float*)d_in[15];
  const float* lno_g  = (const float*)d_in[16], *lno_b  = (const float*)d_in[17];
  const float* o_in_w = (const float*)d_in[18], *o_in_b = (const float*)d_in[19];
  const float* o_out_w= (const float*)d_in[20], *o_out_b= (const float*)d_in[21];
  const float* lnp_g  = (const float*)d_in[22], *lnp_b  = (const float*)d_in[23];
  const float* w1 = (const float*)d_in[24], *b1 = (const float*)d_in[25];
  const float* w2 = (const float*)d_in[26], *b2 = (const float*)d_in[27];
  float* outp = (float*)d_out;

  float *xln, *kvb, *qb, *s0, *t1, *t2, *qkvb, *hid;
  cudaGetSymbolAddress((void**)&xln,  g_xln);
  cudaGetSymbolAddress((void**)&kvb,  g_kvb);
  cudaGetSymbolAddress((void**)&qb,   g_qb);
  cudaGetSymbolAddress((void**)&s0,   g_s0);
  cudaGetSymbolAddress((void**)&t1,   g_t1);
  cudaGetSymbolAddress((void**)&t2,   g_t2);
  cudaGetSymbolAddress((void**)&qkvb, g_qkvb);
  cudaGetSymbolAddress((void**)&hid,  g_hid);

  cudaFuncSetAttribute(mha_kernel, cudaFuncAttributeMaxDynamicSharedMemorySize, 106496);

  // 1) slots = ln(prev_slots)
  ln_kernel<<<ROWS_S/8, 256>>>(prev_slots, t1, lnq_g, lnq_b, ROWS_S);
  // 2) q = slots @ wq^T * D^-0.5
  gemm_kernel<<<dim3(ROWS_S/128, 3), 256>>>(t1, wq, nullptr, nullptr, qb,
                                            ROWS_S, 192, 192, 192, 0.07216878364870323f, 0);
  // 3) xln = ln(features)
  ln_kernel<<<ROWS_BIG/8, 256>>>(features, xln, lnkv_g, lnkv_b, ROWS_BIG);
  // 4,5) k,v projections (the dominant work) into interleaved kv buffer
  gemm_kernel<<<dim3(ROWS_BIG/128, 3), 256>>>(xln, wk,  nullptr, nullptr, kvb,
                                              ROWS_BIG, 192, 192, 384, 1.f, 0);
  gemm_kernel<<<dim3(ROWS_BIG/128, 3), 256>>>(xln, wvw, nullptr, nullptr, kvb + 192,
                                              ROWS_BIG, 192, 192, 384, 1.f, 0);
  // 6) inverse cross-attention
  invattn_kernel<<<BT, 256>>>(qb, kvb, s0);
  // 7) @ wo^T
  gemm_kernel<<<dim3(8, 3), 256>>>(s0, wo, nullptr, nullptr, t1, ROWS_S, 192, 192, 192, 1.f, 0);
  // 8-11) time attention: ln -> qkv proj -> attn(S=128,B=8,nh=4) -> out proj
  ln_kernel<<<128, 256>>>(t1, t2, lnt_g, lnt_b, ROWS_S);
  gemm_kernel<<<dim3(8, 9), 256>>>(t2, t_in_w, t_in_b, nullptr, qkvb, ROWS_S, 576, 192, 576, 1.f, 0);
  mha_kernel<<<32, 256, (3*128*48 + 64*128)*4>>>(qkvb, t1, 128, 8);
  gemm_kernel<<<dim3(8, 3), 256>>>(t1, t_out_w, t_out_b, nullptr, t2, ROWS_S, 192, 192, 192, 1.f, 0);
  // 12) rearrange (b t) n d -> (b n) t d
  transpose_kernel<<<(ROWS_S*DD)/256, 256>>>(t2, t1);
  // 13-16) object attention: ln -> qkv proj -> attn(S=64,B=16,nh=4) -> out proj
  ln_kernel<<<128, 256>>>(t1, t2, lno_g, lno_b, ROWS_S);
  gemm_kernel<<<dim3(8, 9), 256>>>(t2, o_in_w, o_in_b, nullptr, qkvb, ROWS_S, 576, 192, 576, 1.f, 0);
  mha_kernel<<<64, 256, (3*64*48 + 64*64)*4>>>(qkvb, t1, 64, 16);
  gemm_kernel<<<dim3(8, 3), 256>>>(t1, o_out_w, o_out_b, nullptr, t2, ROWS_S, 192, 192, 192, 1.f, 0);
  // 17-19) ln -> FFN(relu) -> proj + residual(prev_slots)  (raw reinterpret == flat rows)
  ln_kernel<<<128, 256>>>(t2, t1, lnp_g, lnp_b, ROWS_S);
  gemm_kernel<<<dim3(8, 8), 256>>>(t1, w1, b1, nullptr, hid, ROWS_S, 512, 192, 512, 1.f, 1);
  gemm_kernel<<<dim3(8, 3), 256>>>(hid, w2, b2, prev_slots, outp, ROWS_S, 192, 512, 192, 1.f, 0);
}

// round 4
// speedup vs baseline: 1.0707x; 1.0707x over previous
#include <cuda_runtime.h>
#include <cuda_bf16.h>
#include <cstdint>

#define DD 192
#define LL 1024
#define BT 128
#define NS 8
#define ROWS_BIG (BT*LL)   /* 131072 */
#define ROWS_S   (BT*NS)   /* 1024   */

// ---------------- scratch (device globals; no allocs allowed) ----------------
__device__ __nv_bfloat16 g_ah [ROWS_BIG * DD];   // ln(features) hi
__device__ __nv_bfloat16 g_al [ROWS_BIG * DD];   // ln(features) lo
__device__ __nv_bfloat16 g_wh [2 * DD * DD];     // wk|wv hi
__device__ __nv_bfloat16 g_wl [2 * DD * DD];     // wk|wv lo
__device__ float g_kvb [ROWS_BIG * 384];         // k | v interleaved per row
__device__ float g_qb  [ROWS_S * DD];
__device__ float g_s0  [ROWS_S * DD];
__device__ float g_t1  [ROWS_S * DD];
__device__ float g_t2  [ROWS_S * DD];
__device__ float g_qkvb[ROWS_S * 576];
__device__ float g_hid [ROWS_S * 512];

// ---------------- LayerNorm (fp32 out): one warp per row of 192 ----------------
__global__ void ln_kernel(const float* __restrict__ x, float* __restrict__ y,
                          const float* __restrict__ g, const float* __restrict__ b,
                          int rows) {
  int w = (blockIdx.x * blockDim.x + threadIdx.x) >> 5;
  int lane = threadIdx.x & 31;
  if (w >= rows) return;
  const float* xr = x + (size_t)w * DD;
  float v[6]; float s = 0.f, s2 = 0.f;
#pragma unroll
  for (int j = 0; j < 6; j++) { float t = xr[j*32 + lane]; v[j]=t; s+=t; s2+=t*t; }
#pragma unroll
  for (int o = 16; o; o >>= 1) {
    s  += __shfl_xor_sync(0xffffffffu, s,  o);
    s2 += __shfl_xor_sync(0xffffffffu, s2, o);
  }
  float m = s * (1.f/DD);
  float inv = rsqrtf(fmaxf(s2*(1.f/DD) - m*m, 0.f) + 1e-5f);
  float* yr = y + (size_t)w * DD;
#pragma unroll
  for (int j = 0; j < 6; j++) { int d = j*32+lane; yr[d] = (v[j]-m)*inv*g[d] + b[d]; }
}

// ---------------- LayerNorm -> bf16 hi/lo split ----------------
__global__ void ln_split_kernel(const float* __restrict__ x,
                                __nv_bfloat16* __restrict__ yh, __nv_bfloat16* __restrict__ yl,
                                const float* __restrict__ g, const float* __restrict__ b,
                                int rows) {
  int w = (blockIdx.x * blockDim.x + threadIdx.x) >> 5;
  int lane = threadIdx.x & 31;
  if (w >= rows) return;
  const float* xr = x + (size_t)w * DD;
  float v[6]; float s = 0.f, s2 = 0.f;
#pragma unroll
  for (int j = 0; j < 6; j++) { float t = xr[j*32 + lane]; v[j]=t; s+=t; s2+=t*t; }
#pragma unroll
  for (int o = 16; o; o >>= 1) {
    s  += __shfl_xor_sync(0xffffffffu, s,  o);
    s2 += __shfl_xor_sync(0xffffffffu, s2, o);
  }
  float m = s * (1.f/DD);
  float inv = rsqrtf(fmaxf(s2*(1.f/DD) - m*m, 0.f) + 1e-5f);
  __nv_bfloat16* yhr = yh + (size_t)w * DD;
  __nv_bfloat16* ylr = yl + (size_t)w * DD;
#pragma unroll
  for (int j = 0; j < 6; j++) {
    int d = j*32+lane;
    float val = (v[j]-m)*inv*g[d] + b[d];
    __nv_bfloat16 h = __float2bfloat16(val);
    yhr[d] = h;
    ylr[d] = __float2bfloat16(val - __bfloat162float(h));
  }
}

// ---------------- W hi/lo split ----------------
__global__ void wsplit_kernel(const float* __restrict__ wk, const float* __restrict__ wv,
                              __nv_bfloat16* __restrict__ wh, __nv_bfloat16* __restrict__ wl) {
  int i = blockIdx.x * 256 + threadIdx.x;
  if (i >= 2 * DD * DD) return;
  float v = (i < DD*DD) ? wk[i] : wv[i - DD*DD];
  __nv_bfloat16 h = __float2bfloat16(v);
  wh[i] = h;
  wl[i] = __float2bfloat16(v - __bfloat162float(h));
}

// ================= mma.sync bf16 GEMM for K/V projections =================
// C(128x96) per CTA; A(128x192) hi/lo + W(96x192) hi/lo resident in smem.
// 3-term split: Ah*Wh + Ah*Wl + Al*Wh. 8 warps (4x2), warp tile 32x48.
#define TCS 200                      /* smem row stride in bf16 elems */
#define SM_AH 0
#define SM_AL (128*TCS)
#define SM_WH (256*TCS)
#define SM_WL (256*TCS + 96*TCS)
#define TC_SMEM_ELEMS (256*TCS + 192*TCS)
#define TC_SMEM_BYTES (TC_SMEM_ELEMS*2)   /* 179200 */

__device__ __forceinline__ uint32_t smem_u32(const void* p) {
  uint32_t a;
  asm("{ .reg .u64 t; cvta.to.shared.u64 t, %1; cvt.u32.u64 %0, t; }" : "=r"(a) : "l"(p));
  return a;
}
__device__ __forceinline__ void ldsm4(uint32_t& r0, uint32_t& r1, uint32_t& r2, uint32_t& r3, uint32_t addr) {
  asm volatile("ldmatrix.sync.aligned.m8n8.x4.shared.b16 {%0,%1,%2,%3}, [%4];"
    : "=r"(r0), "=r"(r1), "=r"(r2), "=r"(r3) : "r"(addr));
}
__device__ __forceinline__ void mma16816(float* c, const uint32_t* a, const uint32_t* b) {
  asm volatile("mma.sync.aligned.m16n8k16.row.col.f32.bf16.bf16.f32 "
    "{%0,%1,%2,%3}, {%4,%5,%6,%7}, {%8,%9}, {%0,%1,%2,%3};"
    : "+f"(c[0]), "+f"(c[1]), "+f"(c[2]), "+f"(c[3])
    : "r"(a[0]), "r"(a[1]), "r"(a[2]), "r"(a[3]), "r"(b[0]), "r"(b[1]));
}

__global__ __launch_bounds__(256)
void tc_mma_kernel(const __nv_bfloat16* __restrict__ ah, const __nv_bfloat16* __restrict__ al,
                   const __nv_bfloat16* __restrict__ wh, const __nv_bfloat16* __restrict__ wl,
                   float* __restrict__ out) {
  extern __shared__ __align__(16) __nv_bfloat16 smem[];
  int t = threadIdx.x, wid = t >> 5, lane = t & 31;
  int tile = blockIdx.x;                 // 0..3: wsel = tile>>1, n0 = (tile&1)*96
  int m0 = blockIdx.y * 128;
  int wsel = tile >> 1;
  int n0 = (tile & 1) * 96;

  // ---- load tiles: straight row-major copy, 16B units (24 per row) ----
  {
    const uint4* As = (const uint4*)(ah + (size_t)m0 * DD);
    const uint4* Ls = (const uint4*)(al + (size_t)m0 * DD);
    uint4* Ad = (uint4*)(smem + SM_AH);
    uint4* Ld = (uint4*)(smem + SM_AL);
    for (int u = t; u < 128*24; u += 256) {
      int r = u / 24, c = u - r*24;
      int dst = (r * TCS) / 8 + c;       // TCS/8 = 25 uint4 per row
      Ad[dst] = As[r*24 + c];
      Ld[dst] = Ls[r*24 + c];
    }
    const uint4* Ws = (const uint4*)(wh + (size_t)wsel*DD*DD + (size_t)n0*DD);
    const uint4* Vs = (const uint4*)(wl + (size_t)wsel*DD*DD + (size_t)n0*DD);
    uint4* Wd = (uint4*)(smem + SM_WH);
    uint4* Vd = (uint4*)(smem + SM_WL);
    for (int u = t; u < 96*24; u += 256) {
      int r = u / 24, c = u - r*24;
      int dst = (r * TCS) / 8 + c;
      Wd[dst] = Ws[r*24 + c];
      Vd[dst] = Vs[r*24 + c];
    }
  }
  __syncthreads();

  int wm = (wid & 3) * 32;               // warp M offset (0,32,64,96)
  int wn = (wid >> 2) * 48;              // warp N offset (0,48)

  uint32_t sbase = smem_u32(smem);
  // ldmatrix thread-address components
  int a_row = (lane & 15);               // rows within 16-row tile
  int a_kh  = (lane >> 4) * 8;           // k half
  int b_row = (lane & 7) + ((lane >> 4) << 3);  // n within 16
  int b_kh  = ((lane >> 3) & 1) * 8;

  float acc[2][6][4];
#pragma unroll
  for (int i = 0; i < 2; i++)
#pragma unroll
    for (int j = 0; j < 6; j++)
#pragma unroll
      for (int q = 0; q < 4; q++) acc[i][j][q] = 0.f;

  const int aoff[3] = { SM_AH, SM_AH, SM_AL };
  const int woff[3] = { SM_WH, SM_WL, SM_WH };
#pragma unroll
  for (int term = 0; term < 3; term++) {
    uint32_t abase = sbase + 2*(uint32_t)aoff[term];
    uint32_t wbase = sbase + 2*(uint32_t)woff[term];
#pragma unroll
    for (int kc = 0; kc < 12; kc++) {
      int k0 = kc * 16;
      uint32_t a[2][4];
#pragma unroll
      for (int i = 0; i < 2; i++) {
        uint32_t addr = abase + 2*(uint32_t)((wm + i*16 + a_row) * TCS + k0 + a_kh);
        ldsm4(a[i][0], a[i][1], a[i][2], a[i][3], addr);
      }
      uint32_t b[6][2];
#pragma unroll
      for (int p = 0; p < 3; p++) {
        uint32_t addr = wbase + 2*(uint32_t)((wn + p*16 + b_row) * TCS + k0 + b_kh);
        uint32_t r0, r1, r2, r3;
        ldsm4(r0, r1, r2, r3, addr);
        b[p*2][0] = r0; b[p*2][1] = r1; b[p*2+1][0] = r2; b[p*2+1][1] = r3;
      }
#pragma unroll
      for (int i = 0; i < 2; i++)
#pragma unroll
        for (int j = 0; j < 6; j++)
          mma16816(acc[i][j], a[i], b[j]);
    }
  }

  // ---- epilogue: c rows = wm + i*16 + lane/4 (+8), cols = wn + j*8 + (lane%4)*2 ----
  int cr = lane >> 2, cc = (lane & 3) * 2;
#pragma unroll
  for (int i = 0; i < 2; i++) {
#pragma unroll
    for (int half = 0; half < 2; half++) {
      int m = m0 + wm + i*16 + cr + half*8;
      float* orow = out + (size_t)m * 384 + wsel * 192 + n0;
#pragma unroll
      for (int j = 0; j < 6; j++) {
        float2 v;
        v.x = acc[i][j][half*2 + 0];
        v.y = acc[i][j][half*2 + 1];
        *(float2*)(orow + wn + j*8 + cc) = v;
      }
    }
  }
}

// ---------------- packed f32x2 helpers (FFMA2) for SIMT GEMM ----------------
__device__ __forceinline__ unsigned long long dup2(float x) {
  unsigned long long r;
  asm("mov.b64 %0, {%1, %1};" : "=l"(r) : "f"(x));
  return r;
}
__device__ __forceinline__ void ffma2(unsigned long long& d, unsigned long long a, unsigned long long b) {
  asm("fma.rn.f32x2 %0, %1, %2, %0;" : "+l"(d) : "l"(a), "l"(b));
}

// ---------------- generic SIMT GEMM (small stages) ----------------
#define GBM 128
#define GBN 64
#define GBK 16
__global__ __launch_bounds__(256)
void gemm_kernel(const float* __restrict__ A, const float* __restrict__ W,
                 const float* __restrict__ bias, const float* __restrict__ res,
                 float* __restrict__ C, int M, int Ncols, int K, int ldc,
                 float alpha, int relu) {
  __shared__ __align__(16) float As[GBK][GBM+4];
  __shared__ __align__(16) float Ws[GBK][GBN+4];
  int t  = threadIdx.x;
  int m0 = blockIdx.x * GBM;
  int n0 = blockIdx.y * GBN;
  int lr = t >> 2;
  int lc = (t & 3) << 2;
  const float* Ap0 = A + (size_t)(m0 + lr)      * K + lc;
  const float* Ap1 = A + (size_t)(m0 + lr + 64) * K + lc;
  const float* Wp  = W + (size_t)(n0 + lr)      * K + lc;
  int ty = t >> 4, tx = t & 15;
  unsigned long long acc[4][4] = {};

  for (int k0 = 0; k0 < K; k0 += GBK) {
    float4 a0 = *(const float4*)(Ap0 + k0);
    float4 a1 = *(const float4*)(Ap1 + k0);
    float4 w0 = *(const float4*)(Wp  + k0);
    __syncthreads();
    As[lc+0][lr]    = a0.x; As[lc+1][lr]    = a0.y; As[lc+2][lr]    = a0.z; As[lc+3][lr]    = a0.w;
    As[lc+0][lr+64] = a1.x; As[lc+1][lr+64] = a1.y; As[lc+2][lr+64] = a1.z; As[lc+3][lr+64] = a1.w;
    Ws[lc+0][lr]    = w0.x; Ws[lc+1][lr]    = w0.y; Ws[lc+2][lr]    = w0.z; Ws[lc+3][lr]    = w0.w;
    __syncthreads();
#pragma unroll
    for (int k = 0; k < GBK; k++) {
      const ulonglong2* ap = (const ulonglong2*)&As[k][ty*8];
      ulonglong2 p0 = ap[0];
      ulonglong2 p1 = ap[1];
      float4 wv = *(const float4*)&Ws[k][tx*4];
      unsigned long long wd0 = dup2(wv.x), wd1 = dup2(wv.y), wd2 = dup2(wv.z), wd3 = dup2(wv.w);
      ffma2(acc[0][0], p0.x, wd0); ffma2(acc[0][1], p0.x, wd1); ffma2(acc[0][2], p0.x, wd2); ffma2(acc[0][3], p0.x, wd3);
      ffma2(acc[1][0], p0.y, wd0); ffma2(acc[1][1], p0.y, wd1); ffma2(acc[1][2], p0.y, wd2); ffma2(acc[1][3], p0.y, wd3);
      ffma2(acc[2][0], p1.x, wd0); ffma2(acc[2][1], p1.x, wd1); ffma2(acc[2][2], p1.x, wd2); ffma2(acc[2][3], p1.x, wd3);
      ffma2(acc[3][0], p1.y, wd0); ffma2(acc[3][1], p1.y, wd1); ffma2(acc[3][2], p1.y, wd2); ffma2(acc[3][3], p1.y, wd3);
    }
  }
#pragma unroll
  for (int ip = 0; ip < 4; ip++) {
#pragma unroll
    for (int j = 0; j < 4; j++) {
      float lo, hi;
      asm("mov.b64 {%0, %1}, %2;" : "=f"(lo), "=f"(hi) : "l"(acc[ip][j]));
      int n = n0 + tx*4 + j;
      int m = m0 + ty*8 + ip*2;
      float bv = bias ? bias[n] : 0.f;
      float v0 = lo*alpha + bv;
      float v1 = hi*alpha + bv;
      if (relu) { v0 = fmaxf(v0, 0.f); v1 = fmaxf(v1, 0.f); }
      if (res)  { v0 += res[(size_t)m*Ncols + n]; v1 += res[(size_t)(m+1)*Ncols + n]; }
      C[(size_t)m*ldc + n]     = v0;
      C[(size_t)(m+1)*ldc + n] = v1;
    }
  }
}

// ---------------- inverse cross-attention (one block per bt) ----------------
__global__ __launch_bounds__(256)
void invattn_kernel(const float* __restrict__ q, const float* __restrict__ kv,
                    float* __restrict__ out) {
  __shared__ float qs[NS][DD];
  __shared__ float sc[NS][LL];
  __shared__ float den[NS];
  int bt = blockIdx.x;
  int t  = threadIdx.x;
  for (int i = t; i < NS*DD; i += 256) qs[i/DD][i%DD] = q[(size_t)bt*NS*DD + i];
  if (t < NS) den[t] = 0.f;
  __syncthreads();

  int warp = t >> 5, lane = t & 31;
  const float* kvb = kv + (size_t)bt * LL * 384;
  for (int s = warp; s < LL; s += 8) {
    const float* kr = kvb + (size_t)s * 384;
    float kk[6];
#pragma unroll
    for (int j = 0; j < 6; j++) kk[j] = kr[j*32 + lane];
#pragma unroll
    for (int n = 0; n < NS; n++) {
      float p = 0.f;
#pragma unroll
      for (int j = 0; j < 6; j++) p += kk[j] * qs[n][j*32 + lane];
#pragma unroll
      for (int o = 16; o; o >>= 1) p += __shfl_xor_sync(0xffffffffu, p, o);
      if (lane == 0) sc[n][s] = p;
    }
  }
  __syncthreads();

  float pd[NS] = {};
  for (int s = t; s < LL; s += 256) {
    float vN[NS]; float mx = -1e30f;
#pragma unroll
    for (int n = 0; n < NS; n++) { vN[n] = sc[n][s]; mx = fmaxf(mx, vN[n]); }
    float sum = 0.f;
#pragma unroll
    for (int n = 0; n < NS; n++) { vN[n] = __expf(vN[n] - mx); sum += vN[n]; }
    float r = 1.f / sum;
#pragma unroll
    for (int n = 0; n < NS; n++) { float wv = vN[n]*r; sc[n][s] = wv; pd[n] += wv; }
  }
#pragma unroll
  for (int n = 0; n < NS; n++) atomicAdd(&den[n], pd[n]);
  __syncthreads();

  if (t < DD) {
    float acc[NS] = {};
    const float* vb = kvb + 192 + t;
#pragma unroll 4
    for (int s = 0; s < LL; s++) {
      float vv = vb[(size_t)s * 384];
#pragma unroll
      for (int n = 0; n < NS; n++) acc[n] += sc[n][s] * vv;
    }
#pragma unroll
    for (int n = 0; n < NS; n++)
      out[((size_t)bt*NS + n)*DD + t] = acc[n] / den[n];
  }
}

// ---------------- standard MHA core: one block per (batch,head); nh=4, hd=48
__global__ __launch_bounds__(256)
void mha_kernel(const float* __restrict__ qkv, float* __restrict__ out, int S, int Bb) {
  extern __shared__ __align__(16) float smbuf[];
  int b = blockIdx.x >> 2, h = blockIdx.x & 3;
  float* qs = smbuf;
  float* ks = qs + S*48;
  float* vs = ks + S*48;
  float* sc = vs + S*48;
  int t = threadIdx.x;
  for (int i = t; i < S*48; i += 256) {
    int s = i / 48, e = i - s*48;
    size_t ro = ((size_t)s*Bb + b)*576 + h*48 + e;
    qs[i] = qkv[ro]; ks[i] = qkv[ro + 192]; vs[i] = qkv[ro + 384];
  }
  __syncthreads();
  const float scale = 0.14433756729740643f;
  const int QC = 64;
  for (int i0 = 0; i0 < S; i0 += QC) {
    for (int idx = t; idx < QC*S; idx += 256) {
      int i = idx / S, s = idx - i*S;
      const float4* qr = (const float4*)(qs + (i0+i)*48);
      const float4* kr = (const float4*)(ks + s*48);
      float p = 0.f;
#pragma unroll
      for (int j = 0; j < 12; j++) {
        float4 a = qr[j]; float4 kx = kr[j];
        p += a.x*kx.x + a.y*kx.y + a.z*kx.z + a.w*kx.w;
      }
      sc[idx] = p * scale;
    }
    __syncthreads();
    int warp = t >> 5, lane = t & 31;
    for (int i = warp; i < QC; i += 8) {
      float mx = -1e30f;
      for (int s = lane; s < S; s += 32) mx = fmaxf(mx, sc[i*S+s]);
#pragma unroll
      for (int o = 16; o; o >>= 1) mx = fmaxf(mx, __shfl_xor_sync(0xffffffffu, mx, o));
      float sum = 0.f;
      for (int s = lane; s < S; s += 32) { float e = __expf(sc[i*S+s]-mx); sc[i*S+s]=e; sum += e; }
#pragma unroll
      for (int o = 16; o; o >>= 1) sum += __shfl_xor_sync(0xffffffffu, sum, o);
      float r = 1.f / sum;
      for (int s = lane; s < S; s += 32) sc[i*S+s] *= r;
    }
    __syncthreads();
    for (int idx = t; idx < QC*48; idx += 256) {
      int i = idx / 48, e = idx - i*48;
      float acc = 0.f;
#pragma unroll 4
      for (int s = 0; s < S; s++) acc += sc[i*S+s] * vs[s*48+e];
      out[((size_t)(i0+i)*Bb + b)*192 + h*48 + e] = acc;
    }
    __syncthreads();
  }
}

// ---------------- (B,T,N,D) -> (B,N,T,D) ----------------
__global__ void transpose_kernel(const float* __restrict__ in, float* __restrict__ out) {
  int idx = blockIdx.x * 256 + threadIdx.x;
  if (idx >= ROWS_S * DD) return;
  int d = idx % DD; int r = idx / DD;
  int n = r & 7; int tt = (r >> 3) & 15; int bb = r >> 7;
  out[(((size_t)bb*8 + n)*16 + tt)*DD + d] = in[idx];
}

// ---------------- launcher ----------------
extern "C" void kernel_launch(void* const* d_in, const int* in_sizes, int n_in,
                              void* d_out, int out_size) {
  const float* features   = (const float*)d_in[0];
  const float* prev_slots = (const float*)d_in[1];
  const float* lnq_g  = (const float*)d_in[2],  *lnq_b  = (const float*)d_in[3];
  const float* lnkv_g = (const float*)d_in[4],  *lnkv_b = (const float*)d_in[5];
  const float* wq = (const float*)d_in[6],  *wk = (const float*)d_in[7];
  const float* wvw= (const float*)d_in[8],  *wo = (const float*)d_in[9];
  const float* lnt_g  = (const float*)d_in[10], *lnt_b  = (const float*)d_in[11];
  const float* t_in_w = (const float*)d_in[12], *t_in_b = (const float*)d_in[13];
  const float* t_out_w= (const float*)d_in[14], *t_out_b= (const float*)d_in[15];
  const float* lno_g  = (const float*)d_in[16], *lno_b  = (const float*)d_in[17];
  const float* o_in_w = (const float*)d_in[18], *o_in_b = (const float*)d_in[19];
  const float* o_out_w= (const float*)d_in[20], *o_out_b= (const float*)d_in[21];
  const float* lnp_g  = (const float*)d_in[22], *lnp_b  = (const float*)d_in[23];
  const float* w1 = (const float*)d_in[24], *b1 = (const float*)d_in[25];
  const float* w2 = (const float*)d_in[26], *b2 = (const float*)d_in[27];
  float* outp = (float*)d_out;

  __nv_bfloat16 *ah, *al, *wh, *wl;
  float *kvb, *qb, *s0, *t1, *t2, *qkvb, *hid;
  cudaGetSymbolAddress((void**)&ah,   g_ah);
  cudaGetSymbolAddress((void**)&al,   g_al);
  cudaGetSymbolAddress((void**)&wh,   g_wh);
  cudaGetSymbolAddress((void**)&wl,   g_wl);
  cudaGetSymbolAddress((void**)&kvb,  g_kvb);
  cudaGetSymbolAddress((void**)&qb,   g_qb);
  cudaGetSymbolAddress((void**)&s0,   g_s0);
  cudaGetSymbolAddress((void**)&t1,   g_t1);
  cudaGetSymbolAddress((void**)&t2,   g_t2);
  cudaGetSymbolAddress((void**)&qkvb, g_qkvb);
  cudaGetSymbolAddress((void**)&hid,  g_hid);

  cudaFuncSetAttribute(mha_kernel, cudaFuncAttributeMaxDynamicSharedMemorySize, 106496);
  cudaFuncSetAttribute(tc_mma_kernel, cudaFuncAttributeMaxDynamicSharedMemorySize, TC_SMEM_BYTES);

  // 1) slots = ln(prev_slots)
  ln_kernel<<<ROWS_S/8, 256>>>(prev_slots, t1, lnq_g, lnq_b, ROWS_S);
  // 2) q = slots @ wq^T * D^-0.5
  gemm_kernel<<<dim3(ROWS_S/128, 3), 256>>>(t1, wq, nullptr, nullptr, qb,
                                            ROWS_S, 192, 192, 192, 0.07216878364870323f, 0);
  // 3) xln = ln(features) -> bf16 hi/lo ; W -> hi/lo
  ln_split_kernel<<<ROWS_BIG/8, 256>>>(features, ah, al, lnkv_g, lnkv_b, ROWS_BIG);
  wsplit_kernel<<<(2*DD*DD + 255)/256, 256>>>(wk, wvw, wh, wl);
  // 4) k,v projections on tensor cores (mma.sync, 3-term bf16 split)
  tc_mma_kernel<<<dim3(4, ROWS_BIG/128), 256, TC_SMEM_BYTES>>>(ah, al, wh, wl, kvb);
  // 6) inverse cross-attention
  invattn_kernel<<<BT, 256>>>(qb, kvb, s0);
  // 7) @ wo^T
  gemm_kernel<<<dim3(8, 3), 256>>>(s0, wo, nullptr, nullptr, t1, ROWS_S, 192, 192, 192, 1.f, 0);
  // 8-11) time attention
  ln_kernel<<<128, 256>>>(t1, t2, lnt_g, lnt_b, ROWS_S);
  gemm_kernel<<<dim3(8, 9), 256>>>(t2, t_in_w, t_in_b, nullptr, qkvb, ROWS_S, 576, 192, 576, 1.f, 0);
  mha_kernel<<<32, 256, (3*128*48 + 64*128)*4>>>(qkvb, t1, 128, 8);
  gemm_kernel<<<dim3(8, 3), 256>>>(t1, t_out_w, t_out_b, nullptr, t2, ROWS_S, 192, 192, 192, 1.f, 0);
  // 12) rearrange
  transpose_kernel<<<(ROWS_S*DD)/256, 256>>>(t2, t1);
  // 13-16) object attention
  ln_kernel<<<128, 256>>>(t1, t2, lno_g, lno_b, ROWS_S);
  gemm_kernel<<<dim3(8, 9), 256>>>(t2, o_in_w, o_in_b, nullptr, qkvb, ROWS_S, 576, 192, 576, 1.f, 0);
  mha_kernel<<<64, 256, (3*64*48 + 64*64)*4>>>(qkvb, t1, 64, 16);
  gemm_kernel<<<dim3(8, 3), 256>>>(t1, o_out_w, o_out_b, nullptr, t2, ROWS_S, 192, 192, 192, 1.f, 0);
  // 17-19) ln -> FFN(relu) -> proj + residual
  ln_kernel<<<128, 256>>>(t2, t1, lnp_g, lnp_b, ROWS_S);
  gemm_kernel<<<dim3(8, 8), 256>>>(t1, w1, b1, nullptr, hid, ROWS_S, 512, 192, 512, 1.f, 1);
  gemm_kernel<<<dim3(8, 3), 256>>>(hid, w2, b2, prev_slots, outp, ROWS_S, 192, 512, 192, 1.f, 0);
}

// round 6
// speedup vs baseline: 2.5929x; 2.4218x over previous
#include <cuda_runtime.h>
#include <cuda_bf16.h>
#include <cstdint>

#define DD 192
#define LL 1024
#define BT 128
#define NS 8
#define ROWS_S   (BT*NS)   /* 1024 */

// ---------------- scratch (device globals; no allocs allowed) ----------------
__device__ float g_qb  [ROWS_S * DD];
__device__ float g_qt  [ROWS_S * DD];
__device__ float g_wkt [DD * DD];
__device__ float g_wvo [DD * DD];
__device__ float g_y   [ROWS_S * DD];
__device__ float g_den [ROWS_S];
__device__ float g_t1  [ROWS_S * DD];
__device__ float g_t2  [ROWS_S * DD];
__device__ float g_qkvb[ROWS_S * 576];
__device__ float g_hid [ROWS_S * 512];

// ---------------- LayerNorm: one warp per row of 192 ----------------
__global__ void ln_kernel(const float* __restrict__ x, float* __restrict__ y,
                          const float* __restrict__ g, const float* __restrict__ b,
                          int rows) {
  int w = (blockIdx.x * blockDim.x + threadIdx.x) >> 5;
  int lane = threadIdx.x & 31;
  if (w >= rows) return;
  const float* xr = x + (size_t)w * DD;
  float v[6]; float s = 0.f, s2 = 0.f;
#pragma unroll
  for (int j = 0; j < 6; j++) { float t = xr[j*32 + lane]; v[j]=t; s+=t; s2+=t*t; }
#pragma unroll
  for (int o = 16; o; o >>= 1) {
    s  += __shfl_xor_sync(0xffffffffu, s,  o);
    s2 += __shfl_xor_sync(0xffffffffu, s2, o);
  }
  float m = s * (1.f/DD);
  float inv = rsqrtf(fmaxf(s2*(1.f/DD) - m*m, 0.f) + 1e-5f);
  float* yr = y + (size_t)w * DD;
#pragma unroll
  for (int j = 0; j < 6; j++) { int d = j*32+lane; yr[d] = (v[j]-m)*inv*g[d] + b[d]; }
}

// ---------------- 192x192 transpose ----------------
__global__ void transpose192_kernel(const float* __restrict__ in, float* __restrict__ out) {
  int i = blockIdx.x, j = threadIdx.x;     // grid 192, block 192
  out[(size_t)j*DD + i] = in[(size_t)i*DD + j];
}

// ---------------- C(192x192) = A(192x192) @ B(192x192) ----------------
__global__ void matmul192_kernel(const float* __restrict__ A, const float* __restrict__ B,
                                 float* __restrict__ C) {
  int i = blockIdx.x, j = threadIdx.x;     // grid 192, block 192
  float acc = 0.f;
#pragma unroll 4
  for (int d = 0; d < DD; d++) acc += A[(size_t)i*DD + d] * B[(size_t)d*DD + j];
  C[(size_t)i*DD + j] = acc;
}

// ---------------- fused LN + inverse cross-attention stream ----------------
// One block per bt (128 blocks, 512 threads = 16 warps, 64 keys/warp).
// Per key s: xln = LN(features_row); p_n = qt_n . xln (8 dots);
// softmax over n (local!); y_n += w_n * xln; den_n += w_n.
__global__ __launch_bounds__(512)
void psb_stream_kernel(const float* __restrict__ features, const float* __restrict__ qt,
                       const float* __restrict__ g, const float* __restrict__ b,
                       float* __restrict__ y, float* __restrict__ den) {
  __shared__ float qs[NS][DD];
  __shared__ float ysum[NS][DD];
  __shared__ float dsum[NS];
  int bt = blockIdx.x;
  int t = threadIdx.x, wid = t >> 5, lane = t & 31;
  for (int i = t; i < NS*DD; i += 512) {
    qs[i/DD][i%DD] = qt[(size_t)bt*NS*DD + i];
    ysum[i/DD][i%DD] = 0.f;
  }
  if (t < NS) dsum[t] = 0.f;
  float gg[6], bb[6];
#pragma unroll
  for (int j = 0; j < 6; j++) { gg[j] = g[j*32+lane]; bb[j] = b[j*32+lane]; }
  __syncthreads();

  float yacc[NS][6];
  float dacc[NS];
#pragma unroll
  for (int n = 0; n < NS; n++) {
    dacc[n] = 0.f;
#pragma unroll
    for (int j = 0; j < 6; j++) yacc[n][j] = 0.f;
  }

  const float* fb = features + (size_t)bt * LL * DD;
  // prefetch first key
  float vn[6];
  {
    const float* xr = fb + (size_t)wid * DD;
#pragma unroll
    for (int j = 0; j < 6; j++) vn[j] = xr[j*32 + lane];
  }
  for (int s = wid; s < LL; s += 16) {
    float v[6];
#pragma unroll
    for (int j = 0; j < 6; j++) v[j] = vn[j];
    int s2i = s + 16;
    if (s2i < LL) {
      const float* xr = fb + (size_t)s2i * DD;
#pragma unroll
      for (int j = 0; j < 6; j++) vn[j] = xr[j*32 + lane];
    }
    // LN
    float sm = 0.f, sq = 0.f;
#pragma unroll
    for (int j = 0; j < 6; j++) { sm += v[j]; sq += v[j]*v[j]; }
#pragma unroll
    for (int o = 16; o; o >>= 1) {
      sm += __shfl_xor_sync(0xffffffffu, sm, o);
      sq += __shfl_xor_sync(0xffffffffu, sq, o);
    }
    float m = sm * (1.f/DD);
    float inv = rsqrtf(fmaxf(sq*(1.f/DD) - m*m, 0.f) + 1e-5f);
#pragma unroll
    for (int j = 0; j < 6; j++) v[j] = (v[j]-m)*inv*gg[j] + bb[j];
    // 8 dots vs qt
    float p[NS];
#pragma unroll
    for (int n = 0; n < NS; n++) {
      float a = 0.f;
#pragma unroll
      for (int j = 0; j < 6; j++) a += v[j] * qs[n][j*32 + lane];
      p[n] = a;
    }
#pragma unroll
    for (int o = 16; o; o >>= 1) {
#pragma unroll
      for (int n = 0; n < NS; n++) p[n] += __shfl_xor_sync(0xffffffffu, p[n], o);
    }
    // local softmax over slots
    float mx = p[0];
#pragma unroll
    for (int n = 1; n < NS; n++) mx = fmaxf(mx, p[n]);
    float ssum = 0.f;
#pragma unroll
    for (int n = 0; n < NS; n++) { p[n] = __expf(p[n]-mx); ssum += p[n]; }
    float r = 1.f / ssum;
#pragma unroll
    for (int n = 0; n < NS; n++) {
      float w = p[n] * r;
      dacc[n] += w;
#pragma unroll
      for (int j = 0; j < 6; j++) yacc[n][j] += w * v[j];
    }
  }
  // merge across warps
#pragma unroll
  for (int n = 0; n < NS; n++)
#pragma unroll
    for (int j = 0; j < 6; j++)
      atomicAdd(&ysum[n][j*32 + lane], yacc[n][j]);
  if (lane == 0)
#pragma unroll
    for (int n = 0; n < NS; n++) atomicAdd(&dsum[n], dacc[n]);
  __syncthreads();
  for (int i = t; i < NS*DD; i += 512)
    y[(size_t)bt*NS*DD + i] = ysum[i/DD][i%DD];
  if (t < NS) den[bt*NS + t] = dsum[t];
}

// ---------------- packed f32x2 helpers (FFMA2) ----------------
__device__ __forceinline__ unsigned long long dup2(float x) {
  unsigned long long r;
  asm("mov.b64 %0, {%1, %1};" : "=l"(r) : "f"(x));
  return r;
}
__device__ __forceinline__ void ffma2(unsigned long long& d, unsigned long long a, unsigned long long b) {
  asm("fma.rn.f32x2 %0, %1, %2, %0;" : "+l"(d) : "l"(a), "l"(b));
}

// ---------------- generic SIMT GEMM: C = alpha*(rowsc.A) @ W^T [+bias][relu][+res] ----------------
#define GBM 128
#define GBN 64
#define GBK 16
__global__ __launch_bounds__(256)
void gemm_kernel(const float* __restrict__ A, const float* __restrict__ W,
                 const float* __restrict__ bias, const float* __restrict__ res,
                 const float* __restrict__ rowdiv,
                 float* __restrict__ C, int M, int Ncols, int K, int ldc,
                 float alpha, int relu) {
  __shared__ __align__(16) float As[GBK][GBM+4];
  __shared__ __align__(16) float Ws[GBK][GBN+4];
  int t  = threadIdx.x;
  int m0 = blockIdx.x * GBM;
  int n0 = blockIdx.y * GBN;
  int lr = t >> 2;
  int lc = (t & 3) << 2;
  const float* Ap0 = A + (size_t)(m0 + lr)      * K + lc;
  const float* Ap1 = A + (size_t)(m0 + lr + 64) * K + lc;
  const float* Wp  = W + (size_t)(n0 + lr)      * K + lc;
  float rs0 = rowdiv ? 1.f / rowdiv[m0 + lr]      : 1.f;
  float rs1 = rowdiv ? 1.f / rowdiv[m0 + lr + 64] : 1.f;
  int ty = t >> 4, tx = t & 15;
  unsigned long long acc[4][4] = {};

  for (int k0 = 0; k0 < K; k0 += GBK) {
    float4 a0 = *(const float4*)(Ap0 + k0);
    float4 a1 = *(const float4*)(Ap1 + k0);
    float4 w0 = *(const float4*)(Wp  + k0);
    a0.x *= rs0; a0.y *= rs0; a0.z *= rs0; a0.w *= rs0;
    a1.x *= rs1; a1.y *= rs1; a1.z *= rs1; a1.w *= rs1;
    __syncthreads();
    As[lc+0][lr]    = a0.x; As[lc+1][lr]    = a0.y; As[lc+2][lr]    = a0.z; As[lc+3][lr]    = a0.w;
    As[lc+0][lr+64] = a1.x; As[lc+1][lr+64] = a1.y; As[lc+2][lr+64] = a1.z; As[lc+3][lr+64] = a1.w;
    Ws[lc+0][lr]    = w0.x; Ws[lc+1][lr]    = w0.y; Ws[lc+2][lr]    = w0.z; Ws[lc+3][lr]    = w0.w;
    __syncthreads();
#pragma unroll
    for (int k = 0; k < GBK; k++) {
      const ulonglong2* ap = (const ulonglong2*)&As[k][ty*8];
      ulonglong2 p0 = ap[0];
      ulonglong2 p1 = ap[1];
      float4 wv = *(const float4*)&Ws[k][tx*4];
      unsigned long long wd0 = dup2(wv.x), wd1 = dup2(wv.y), wd2 = dup2(wv.z), wd3 = dup2(wv.w);
      ffma2(acc[0][0], p0.x, wd0); ffma2(acc[0][1], p0.x, wd1); ffma2(acc[0][2], p0.x, wd2); ffma2(acc[0][3], p0.x, wd3);
      ffma2(acc[1][0], p0.y, wd0); ffma2(acc[1][1], p0.y, wd1); ffma2(acc[1][2], p0.y, wd2); ffma2(acc[1][3], p0.y, wd3);
      ffma2(acc[2][0], p1.x, wd0); ffma2(acc[2][1], p1.x, wd1); ffma2(acc[2][2], p1.x, wd2); ffma2(acc[2][3], p1.x, wd3);
      ffma2(acc[3][0], p1.y, wd0); ffma2(acc[3][1], p1.y, wd1); ffma2(acc[3][2], p1.y, wd2); ffma2(acc[3][3], p1.y, wd3);
    }
  }
#pragma unroll
  for (int ip = 0; ip < 4; ip++) {
#pragma unroll
    for (int j = 0; j < 4; j++) {
      float lo, hi;
      asm("mov.b64 {%0, %1}, %2;" : "=f"(lo), "=f"(hi) : "l"(acc[ip][j]));
      int n = n0 + tx*4 + j;
      int m = m0 + ty*8 + ip*2;
      float bv = bias ? bias[n] : 0.f;
      float v0 = lo*alpha + bv;
      float v1 = hi*alpha + bv;
      if (relu) { v0 = fmaxf(v0, 0.f); v1 = fmaxf(v1, 0.f); }
      if (res)  { v0 += res[(size_t)m*Ncols + n]; v1 += res[(size_t)(m+1)*Ncols + n]; }
      C[(size_t)m*ldc + n]     = v0;
      C[(size_t)(m+1)*ldc + n] = v1;
    }
  }
}

// ---------------- standard MHA core: one block per (batch,head); nh=4, hd=48 ----------------
__global__ __launch_bounds__(256)
void mha_kernel(const float* __restrict__ qkv, float* __restrict__ out, int S, int Bb) {
  extern __shared__ __align__(16) float smbuf[];
  int b = blockIdx.x >> 2, h = blockIdx.x & 3;
  float* qs = smbuf;
  float* ks = qs + S*48;
  float* vs = ks + S*48;
  float* sc = vs + S*48;
  int t = threadIdx.x;
  for (int i = t; i < S*48; i += 256) {
    int s = i / 48, e = i - s*48;
    size_t ro = ((size_t)s*Bb + b)*576 + h*48 + e;
    qs[i] = qkv[ro]; ks[i] = qkv[ro + 192]; vs[i] = qkv[ro + 384];
  }
  __syncthreads();
  const float scale = 0.14433756729740643f;
  const int QC = 64;
  for (int i0 = 0; i0 < S; i0 += QC) {
    for (int idx = t; idx < QC*S; idx += 256) {
      int i = idx / S, s = idx - i*S;
      const float4* qr = (const float4*)(qs + (i0+i)*48);
      const float4* kr = (const float4*)(ks + s*48);
      float p = 0.f;
#pragma unroll
      for (int j = 0; j < 12; j++) {
        float4 a = qr[j]; float4 kx = kr[j];
        p += a.x*kx.x + a.y*kx.y + a.z*kx.z + a.w*kx.w;
      }
      sc[idx] = p * scale;
    }
    __syncthreads();
    int warp = t >> 5, lane = t & 31;
    for (int i = warp; i < QC; i += 8) {
      float mx = -1e30f;
      for (int s = lane; s < S; s += 32) mx = fmaxf(mx, sc[i*S+s]);
#pragma unroll
      for (int o = 16; o; o >>= 1) mx = fmaxf(mx, __shfl_xor_sync(0xffffffffu, mx, o));
      float sum = 0.f;
      for (int s = lane; s < S; s += 32) { float e = __expf(sc[i*S+s]-mx); sc[i*S+s]=e; sum += e; }
#pragma unroll
      for (int o = 16; o; o >>= 1) sum += __shfl_xor_sync(0xffffffffu, sum, o);
      float r = 1.f / sum;
      for (int s = lane; s < S; s += 32) sc[i*S+s] *= r;
    }
    __syncthreads();
    for (int idx = t; idx < QC*48; idx += 256) {
      int i = idx / 48, e = idx - i*48;
      float acc = 0.f;
#pragma unroll 4
      for (int s = 0; s < S; s++) acc += sc[i*S+s] * vs[s*48+e];
      out[((size_t)(i0+i)*Bb + b)*192 + h*48 + e] = acc;
    }
    __syncthreads();
  }
}

// ---------------- (B,T,N,D) -> (B,N,T,D) ----------------
__global__ void transpose_kernel(const float* __restrict__ in, float* __restrict__ out) {
  int idx = blockIdx.x * 256 + threadIdx.x;
  if (idx >= ROWS_S * DD) return;
  int d = idx % DD; int r = idx / DD;
  int n = r & 7; int tt = (r >> 3) & 15; int bb = r >> 7;
  out[(((size_t)bb*8 + n)*16 + tt)*DD + d] = in[idx];
}

// ---------------- launcher ----------------
extern "C" void kernel_launch(void* const* d_in, const int* in_sizes, int n_in,
                              void* d_out, int out_size) {
  const float* features   = (const float*)d_in[0];
  const float* prev_slots = (const float*)d_in[1];
  const float* lnq_g  = (const float*)d_in[2],  *lnq_b  = (const float*)d_in[3];
  const float* lnkv_g = (const float*)d_in[4],  *lnkv_b = (const float*)d_in[5];
  const float* wq = (const float*)d_in[6],  *wk = (const float*)d_in[7];
  const float* wvw= (const float*)d_in[8],  *wo = (const float*)d_in[9];
  const float* lnt_g  = (const float*)d_in[10], *lnt_b  = (const float*)d_in[11];
  const float* t_in_w = (const float*)d_in[12], *t_in_b = (const float*)d_in[13];
  const float* t_out_w= (const float*)d_in[14], *t_out_b= (const float*)d_in[15];
  const float* lno_g  = (const float*)d_in[16], *lno_b  = (const float*)d_in[17];
  const float* o_in_w = (const float*)d_in[18], *o_in_b = (const float*)d_in[19];
  const float* o_out_w= (const float*)d_in[20], *o_out_b= (const float*)d_in[21];
  const float* lnp_g  = (const float*)d_in[22], *lnp_b  = (const float*)d_in[23];
  const float* w1 = (const float*)d_in[24], *b1 = (const float*)d_in[25];
  const float* w2 = (const float*)d_in[26], *b2 = (const float*)d_in[27];
  float* outp = (float*)d_out;

  float *qb, *qt, *wkt, *wvo, *y, *den, *t1, *t2, *qkvb, *hid;
  cudaGetSymbolAddress((void**)&qb,   g_qb);
  cudaGetSymbolAddress((void**)&qt,   g_qt);
  cudaGetSymbolAddress((void**)&wkt,  g_wkt);
  cudaGetSymbolAddress((void**)&wvo,  g_wvo);
  cudaGetSymbolAddress((void**)&y,    g_y);
  cudaGetSymbolAddress((void**)&den,  g_den);
  cudaGetSymbolAddress((void**)&t1,   g_t1);
  cudaGetSymbolAddress((void**)&t2,   g_t2);
  cudaGetSymbolAddress((void**)&qkvb, g_qkvb);
  cudaGetSymbolAddress((void**)&hid,  g_hid);

  cudaFuncSetAttribute(mha_kernel, cudaFuncAttributeMaxDynamicSharedMemorySize, 106496);

  // (0) slots = ln(prev_slots)
  ln_kernel<<<ROWS_S/8, 256>>>(prev_slots, t1, lnq_g, lnq_b, ROWS_S);
  // (1) qb = slots @ wq^T * D^-0.5
  gemm_kernel<<<dim3(ROWS_S/128, 3), 256>>>(t1, wq, nullptr, nullptr, nullptr, qb,
                                            ROWS_S, 192, 192, 192, 0.07216878364870323f, 0);
  // (2) wkT
  transpose192_kernel<<<192, 192>>>(wk, wkt);
  // (3) qt = qb @ wk  (= qb @ (wkT)^T)
  gemm_kernel<<<dim3(ROWS_S/128, 3), 256>>>(qb, wkt, nullptr, nullptr, nullptr, qt,
                                            ROWS_S, 192, 192, 192, 1.f, 0);
  // (4) Wvo = wo @ wv
  matmul192_kernel<<<192, 192>>>(wo, wvw, wvo);
  // (5) fused LN + inverse cross-attention stream (reads features ONCE)
  psb_stream_kernel<<<BT, 512>>>(features, qt, lnkv_g, lnkv_b, y, den);
  // (6) s = (y/den) @ Wvo^T   (= attn output through wv and wo)
  gemm_kernel<<<dim3(ROWS_S/128, 3), 256>>>(y, wvo, nullptr, nullptr, den, t1,
                                            ROWS_S, 192, 192, 192, 1.f, 0);
  // (7-10) time attention
  ln_kernel<<<128, 256>>>(t1, t2, lnt_g, lnt_b, ROWS_S);
  gemm_kernel<<<dim3(8, 9), 256>>>(t2, t_in_w, t_in_b, nullptr, nullptr, qkvb,
                                   ROWS_S, 576, 192, 576, 1.f, 0);
  mha_kernel<<<32, 256, (3*128*48 + 64*128)*4>>>(qkvb, t1, 128, 8);
  gemm_kernel<<<dim3(8, 3), 256>>>(t1, t_out_w, t_out_b, nullptr, nullptr, t2,
                                   ROWS_S, 192, 192, 192, 1.f, 0);
  // (11) rearrange (b t) n d -> (b n) t d
  transpose_kernel<<<(ROWS_S*DD)/256, 256>>>(t2, t1);
  // (12-15) object attention
  ln_kernel<<<128, 256>>>(t1, t2, lno_g, lno_b, ROWS_S);
  gemm_kernel<<<dim3(8, 9), 256>>>(t2, o_in_w, o_in_b, nullptr, nullptr, qkvb,
                                   ROWS_S, 576, 192, 576, 1.f, 0);
  mha_kernel<<<64, 256, (3*64*48 + 64*64)*4>>>(qkvb, t1, 64, 16);
  gemm_kernel<<<dim3(8, 3), 256>>>(t1, o_out_w, o_out_b, nullptr, nullptr, t2,
                                   ROWS_S, 192, 192, 192, 1.f, 0);
  // (16-18) ln -> FFN(relu) -> proj + residual
  ln_kernel<<<128, 256>>>(t2, t1, lnp_g, lnp_b, ROWS_S);
  gemm_kernel<<<dim3(8, 8), 256>>>(t1, w1, b1, nullptr, nullptr, hid,
                                   ROWS_S, 512, 192, 512, 1.f, 1);
  gemm_kernel<<<dim3(8, 3), 256>>>(hid, w2, b2, prev_slots, nullptr, outp,
                                   ROWS_S, 192, 512, 192, 1.f, 0);
}

// round 7
// speedup vs baseline: 3.1892x; 1.2300x over previous
#include <cuda_runtime.h>
#include <cstdint>

#define DD 192
#define LL 1024
#define BT 128
#define NS 8
#define ROWS_S   (BT*NS)   /* 1024 */

// ---------------- scratch (device globals; no allocs allowed) ----------------
__device__ float g_qt  [ROWS_S * DD];
__device__ float g_wkq [DD * DD];
__device__ float g_wvo [DD * DD];
__device__ float g_y   [2 * ROWS_S * DD];
__device__ float g_den [2 * ROWS_S];
__device__ float g_t1  [ROWS_S * DD];
__device__ float g_t2  [ROWS_S * DD];
__device__ float g_qkvb[ROWS_S * 576];
__device__ float g_hid [ROWS_S * 512];

// ---------------- LayerNorm: one warp per row of 192 ----------------
__global__ void ln_kernel(const float* __restrict__ x, float* __restrict__ y,
                          const float* __restrict__ g, const float* __restrict__ b,
                          int rows) {
  int w = (blockIdx.x * blockDim.x + threadIdx.x) >> 5;
  int lane = threadIdx.x & 31;
  if (w >= rows) return;
  const float* xr = x + (size_t)w * DD;
  float v[6]; float s = 0.f, s2 = 0.f;
#pragma unroll
  for (int j = 0; j < 6; j++) { float t = xr[j*32 + lane]; v[j]=t; s+=t; s2+=t*t; }
#pragma unroll
  for (int o = 16; o; o >>= 1) {
    s  += __shfl_xor_sync(0xffffffffu, s,  o);
    s2 += __shfl_xor_sync(0xffffffffu, s2, o);
  }
  float m = s * (1.f/DD);
  float inv = rsqrtf(fmaxf(s2*(1.f/DD) - m*m, 0.f) + 1e-5f);
  float* yr = y + (size_t)w * DD;
#pragma unroll
  for (int j = 0; j < 6; j++) { int d = j*32+lane; yr[d] = (v[j]-m)*inv*g[d] + b[d]; }
}

// ---------------- LayerNorm with permuted read: out row w <- src row (bb*16+tt)*8+n ----------------
__global__ void ln_perm_kernel(const float* __restrict__ x, float* __restrict__ y,
                               const float* __restrict__ g, const float* __restrict__ b) {
  int w = (blockIdx.x * blockDim.x + threadIdx.x) >> 5;
  int lane = threadIdx.x & 31;
  if (w >= ROWS_S) return;
  int bb = w >> 7, n = (w >> 4) & 7, tt = w & 15;
  int sr = (bb*16 + tt)*8 + n;
  const float* xr = x + (size_t)sr * DD;
  float v[6]; float s = 0.f, s2 = 0.f;
#pragma unroll
  for (int j = 0; j < 6; j++) { float t = xr[j*32 + lane]; v[j]=t; s+=t; s2+=t*t; }
#pragma unroll
  for (int o = 16; o; o >>= 1) {
    s  += __shfl_xor_sync(0xffffffffu, s,  o);
    s2 += __shfl_xor_sync(0xffffffffu, s2, o);
  }
  float m = s * (1.f/DD);
  float inv = rsqrtf(fmaxf(s2*(1.f/DD) - m*m, 0.f) + 1e-5f);
  float* yr = y + (size_t)w * DD;
#pragma unroll
  for (int j = 0; j < 6; j++) { int d = j*32+lane; yr[d] = (v[j]-m)*inv*g[d] + b[d]; }
}

// ---------------- C = A @ B (192x192) ----------------
__global__ void matmul192_kernel(const float* __restrict__ A, const float* __restrict__ B,
                                 float* __restrict__ C) {
  int i = blockIdx.x, j = threadIdx.x;
  float acc = 0.f;
#pragma unroll 4
  for (int d = 0; d < DD; d++) acc += A[(size_t)i*DD + d] * B[(size_t)d*DD + j];
  C[(size_t)i*DD + j] = acc;
}
// ---------------- C = A^T @ B (192x192):  C[i][j] = sum_d A[d][i] B[d][j] ----------------
__global__ void matmul192_t_kernel(const float* __restrict__ A, const float* __restrict__ B,
                                   float* __restrict__ C) {
  int i = blockIdx.x, j = threadIdx.x;
  float acc = 0.f;
#pragma unroll 4
  for (int d = 0; d < DD; d++) acc += A[(size_t)d*DD + i] * B[(size_t)d*DD + j];
  C[(size_t)i*DD + j] = acc;
}

// ---------------- fused LN + inverse cross-attention stream (2 blocks per bt) ----------------
__global__ __launch_bounds__(512)
void psb_stream_kernel(const float* __restrict__ features, const float* __restrict__ qt,
                       const float* __restrict__ g, const float* __restrict__ b,
                       float* __restrict__ y, float* __restrict__ den) {
  __shared__ float qs[NS][DD];
  __shared__ float ysum[NS][DD];
  __shared__ float dsum[NS];
  int bt = blockIdx.x;
  int half = blockIdx.y;
  int t = threadIdx.x, wid = t >> 5, lane = t & 31;
  for (int i = t; i < NS*DD; i += 512) {
    qs[i/DD][i%DD] = qt[(size_t)bt*NS*DD + i];
    ysum[i/DD][i%DD] = 0.f;
  }
  if (t < NS) dsum[t] = 0.f;
  float gg[6], bb[6];
#pragma unroll
  for (int j = 0; j < 6; j++) { gg[j] = g[j*32+lane]; bb[j] = b[j*32+lane]; }
  __syncthreads();

  float yacc[NS][6];
  float dacc[NS];
#pragma unroll
  for (int n = 0; n < NS; n++) {
    dacc[n] = 0.f;
#pragma unroll
    for (int j = 0; j < 6; j++) yacc[n][j] = 0.f;
  }

  const float* fb = features + (size_t)bt * LL * DD;
  int s_begin = half * 512 + wid;
  int s_end   = half * 512 + 512;
  float vn[6];
  {
    const float* xr = fb + (size_t)s_begin * DD;
#pragma unroll
    for (int j = 0; j < 6; j++) vn[j] = xr[j*32 + lane];
  }
  for (int s = s_begin; s < s_end; s += 16) {
    float v[6];
#pragma unroll
    for (int j = 0; j < 6; j++) v[j] = vn[j];
    int s2i = s + 16;
    if (s2i < s_end) {
      const float* xr = fb + (size_t)s2i * DD;
#pragma unroll
      for (int j = 0; j < 6; j++) vn[j] = xr[j*32 + lane];
    }
    float sm = 0.f, sq = 0.f;
#pragma unroll
    for (int j = 0; j < 6; j++) { sm += v[j]; sq += v[j]*v[j]; }
#pragma unroll
    for (int o = 16; o; o >>= 1) {
      sm += __shfl_xor_sync(0xffffffffu, sm, o);
      sq += __shfl_xor_sync(0xffffffffu, sq, o);
    }
    float m = sm * (1.f/DD);
    float inv = rsqrtf(fmaxf(sq*(1.f/DD) - m*m, 0.f) + 1e-5f);
#pragma unroll
    for (int j = 0; j < 6; j++) v[j] = (v[j]-m)*inv*gg[j] + bb[j];
    float p[NS];
#pragma unroll
    for (int n = 0; n < NS; n++) {
      float a = 0.f;
#pragma unroll
      for (int j = 0; j < 6; j++) a += v[j] * qs[n][j*32 + lane];
      p[n] = a;
    }
#pragma unroll
    for (int o = 16; o; o >>= 1) {
#pragma unroll
      for (int n = 0; n < NS; n++) p[n] += __shfl_xor_sync(0xffffffffu, p[n], o);
    }
    float mx = p[0];
#pragma unroll
    for (int n = 1; n < NS; n++) mx = fmaxf(mx, p[n]);
    float ssum = 0.f;
#pragma unroll
    for (int n = 0; n < NS; n++) { p[n] = __expf(p[n]-mx); ssum += p[n]; }
    float r = 1.f / ssum;
#pragma unroll
    for (int n = 0; n < NS; n++) {
      float w = p[n] * r;
      dacc[n] += w;
#pragma unroll
      for (int j = 0; j < 6; j++) yacc[n][j] += w * v[j];
    }
  }
#pragma unroll
  for (int n = 0; n < NS; n++)
#pragma unroll
    for (int j = 0; j < 6; j++)
      atomicAdd(&ysum[n][j*32 + lane], yacc[n][j]);
  if (lane == 0)
#pragma unroll
    for (int n = 0; n < NS; n++) atomicAdd(&dsum[n], dacc[n]);
  __syncthreads();
  float* yp = y + (size_t)half * ROWS_S * DD + (size_t)bt*NS*DD;
  for (int i = t; i < NS*DD; i += 512) yp[i] = ysum[i/DD][i%DD];
  if (t < NS) den[half*ROWS_S + bt*NS + t] = dsum[t];
}

// ---------------- packed f32x2 helpers ----------------
__device__ __forceinline__ unsigned long long dup2(float x) {
  unsigned long long r;
  asm("mov.b64 %0, {%1, %1};" : "=l"(r) : "f"(x));
  return r;
}
__device__ __forceinline__ void ffma2(unsigned long long& d, unsigned long long a, unsigned long long b) {
  asm("fma.rn.f32x2 %0, %1, %2, %0;" : "+l"(d) : "l"(a), "l"(b));
}

// ---------------- small-tile GEMM: C(MxN) = alpha*((A[+A2])/rowdiv) @ W^T [+bias][relu][+res]
// tile 32(M) x 64(N) x 16(K), 256 threads, 2x4 micro-tile.
__global__ __launch_bounds__(256)
void gemm_s(const float* __restrict__ A, const float* __restrict__ A2,
            const float* __restrict__ W,
            const float* __restrict__ bias, const float* __restrict__ res,
            const float* __restrict__ rowdiv, const float* __restrict__ rowdiv2,
            float* __restrict__ C, int M, int Ncols, int K, int ldc,
            float alpha, int relu) {
  __shared__ __align__(16) float As[16][36];
  __shared__ __align__(16) float Ws[16][68];
  int t = threadIdx.x;
  int m0 = blockIdx.x * 32, n0 = blockIdx.y * 64;
  int lrA = t >> 2, lcA = (t & 3) << 2;       // valid for t<128
  int lrW = t >> 2, lcW = (t & 3) << 2;       // all 256 threads: rows 0..63
  const float* Ap  = A + (size_t)(m0 + (lrA & 31)) * K + lcA;
  const float* Ap2 = A2 ? A2 + (size_t)(m0 + (lrA & 31)) * K + lcA : nullptr;
  const float* Wp  = W + (size_t)(n0 + lrW) * K + lcW;
  float rsA = 1.f;
  if (rowdiv && t < 128) {
    float d = rowdiv[m0 + lrA];
    if (rowdiv2) d += rowdiv2[m0 + lrA];
    rsA = 1.f / d;
  }
  int ty = t >> 4, tx = t & 15;
  unsigned long long acc[4] = {};

  for (int k0 = 0; k0 < K; k0 += 16) {
    float4 a0 = make_float4(0.f,0.f,0.f,0.f);
    if (t < 128) {
      a0 = *(const float4*)(Ap + k0);
      if (Ap2) {
        float4 a2 = *(const float4*)(Ap2 + k0);
        a0.x += a2.x; a0.y += a2.y; a0.z += a2.z; a0.w += a2.w;
      }
      a0.x *= rsA; a0.y *= rsA; a0.z *= rsA; a0.w *= rsA;
    }
    float4 w0 = *(const float4*)(Wp + k0);
    __syncthreads();
    if (t < 128) {
      As[lcA+0][lrA] = a0.x; As[lcA+1][lrA] = a0.y;
      As[lcA+2][lrA] = a0.z; As[lcA+3][lrA] = a0.w;
    }
    Ws[lcW+0][lrW] = w0.x; Ws[lcW+1][lrW] = w0.y;
    Ws[lcW+2][lrW] = w0.z; Ws[lcW+3][lrW] = w0.w;
    __syncthreads();
#pragma unroll
    for (int k = 0; k < 16; k++) {
      unsigned long long ap = *(const unsigned long long*)&As[k][ty*2];
      float4 wv = *(const float4*)&Ws[k][tx*4];
      ffma2(acc[0], ap, dup2(wv.x));
      ffma2(acc[1], ap, dup2(wv.y));
      ffma2(acc[2], ap, dup2(wv.z));
      ffma2(acc[3], ap, dup2(wv.w));
    }
  }

  int m = m0 + ty*2, n = n0 + tx*4;
  float r0[4], r1[4];
#pragma unroll
  for (int j = 0; j < 4; j++) {
    float lo, hi;
    asm("mov.b64 {%0, %1}, %2;" : "=f"(lo), "=f"(hi) : "l"(acc[j]));
    float bv = bias ? bias[n+j] : 0.f;
    float v0 = lo*alpha + bv;
    float v1 = hi*alpha + bv;
    if (relu) { v0 = fmaxf(v0, 0.f); v1 = fmaxf(v1, 0.f); }
    if (res)  { v0 += res[(size_t)m*Ncols + n+j]; v1 += res[(size_t)(m+1)*Ncols + n+j]; }
    r0[j] = v0; r1[j] = v1;
  }
  *(float4*)(C + (size_t)m*ldc + n)     = make_float4(r0[0], r0[1], r0[2], r0[3]);
  *(float4*)(C + (size_t)(m+1)*ldc + n) = make_float4(r1[0], r1[1], r1[2], r1[3]);
}

// ---------------- MHA core, query-chunked: grid (Bb*4, S/64); nh=4, hd=48 ----------------
__global__ __launch_bounds__(256)
void mha_kernel(const float* __restrict__ qkv, float* __restrict__ out, int S, int Bb) {
  extern __shared__ __align__(16) float smbuf[];
  int b = blockIdx.x >> 2, h = blockIdx.x & 3;
  int i0 = blockIdx.y * 64;
  float* qs = smbuf;           // 64*48
  float* ks = qs + 64*48;      // S*48
  float* vs = ks + S*48;       // S*48
  float* sc = vs + S*48;       // 64*S
  int t = threadIdx.x;
  for (int i = t; i < 64*48; i += 256) {
    int s = i / 48, e = i - s*48;
    qs[i] = qkv[((size_t)(i0+s)*Bb + b)*576 + h*48 + e];
  }
  for (int i = t; i < S*48; i += 256) {
    int s = i / 48, e = i - s*48;
    size_t ro = ((size_t)s*Bb + b)*576 + h*48 + e;
    ks[i] = qkv[ro + 192]; vs[i] = qkv[ro + 384];
  }
  __syncthreads();
  const float scale = 0.14433756729740643f;  // 1/sqrt(48)
  for (int idx = t; idx < 64*S; idx += 256) {
    int i = idx / S, s = idx - i*S;
    const float4* qr = (const float4*)(qs + i*48);
    const float4* kr = (const float4*)(ks + s*48);
    float p = 0.f;
#pragma unroll
    for (int j = 0; j < 12; j++) {
      float4 a = qr[j]; float4 kx = kr[j];
      p += a.x*kx.x + a.y*kx.y + a.z*kx.z + a.w*kx.w;
    }
    sc[idx] = p * scale;
  }
  __syncthreads();
  int warp = t >> 5, lane = t & 31;
  for (int i = warp; i < 64; i += 8) {
    float mx = -1e30f;
    for (int s = lane; s < S; s += 32) mx = fmaxf(mx, sc[i*S+s]);
#pragma unroll
    for (int o = 16; o; o >>= 1) mx = fmaxf(mx, __shfl_xor_sync(0xffffffffu, mx, o));
    float sum = 0.f;
    for (int s = lane; s < S; s += 32) { float e = __expf(sc[i*S+s]-mx); sc[i*S+s]=e; sum += e; }
#pragma unroll
    for (int o = 16; o; o >>= 1) sum += __shfl_xor_sync(0xffffffffu, sum, o);
    float r = 1.f / sum;
    for (int s = lane; s < S; s += 32) sc[i*S+s] *= r;
  }
  __syncthreads();
  for (int idx = t; idx < 64*48; idx += 256) {
    int i = idx / 48, e = idx - i*48;
    float acc = 0.f;
#pragma unroll 4
    for (int s = 0; s < S; s++) acc += sc[i*S+s] * vs[s*48+e];
    out[((size_t)(i0+i)*Bb + b)*192 + h*48 + e] = acc;
  }
}

// ---------------- launcher ----------------
extern "C" void kernel_launch(void* const* d_in, const int* in_sizes, int n_in,
                              void* d_out, int out_size) {
  const float* features   = (const float*)d_in[0];
  const float* prev_slots = (const float*)d_in[1];
  const float* lnq_g  = (const float*)d_in[2],  *lnq_b  = (const float*)d_in[3];
  const float* lnkv_g = (const float*)d_in[4],  *lnkv_b = (const float*)d_in[5];
  const float* wq = (const float*)d_in[6],  *wk = (const float*)d_in[7];
  const float* wvw= (const float*)d_in[8],  *wo = (const float*)d_in[9];
  const float* lnt_g  = (const float*)d_in[10], *lnt_b  = (const float*)d_in[11];
  const float* t_in_w = (const float*)d_in[12], *t_in_b = (const float*)d_in[13];
  const float* t_out_w= (const float*)d_in[14], *t_out_b= (const float*)d_in[15];
  const float* lno_g  = (const float*)d_in[16], *lno_b  = (const float*)d_in[17];
  const float* o_in_w = (const float*)d_in[18], *o_in_b = (const float*)d_in[19];
  const float* o_out_w= (const float*)d_in[20], *o_out_b= (const float*)d_in[21];
  const float* lnp_g  = (const float*)d_in[22], *lnp_b  = (const float*)d_in[23];
  const float* w1 = (const float*)d_in[24], *b1 = (const float*)d_in[25];
  const float* w2 = (const float*)d_in[26], *b2 = (const float*)d_in[27];
  float* outp = (float*)d_out;

  float *qt, *wkq, *wvo, *y, *den, *t1, *t2, *qkvb, *hid;
  cudaGetSymbolAddress((void**)&qt,   g_qt);
  cudaGetSymbolAddress((void**)&wkq,  g_wkq);
  cudaGetSymbolAddress((void**)&wvo,  g_wvo);
  cudaGetSymbolAddress((void**)&y,    g_y);
  cudaGetSymbolAddress((void**)&den,  g_den);
  cudaGetSymbolAddress((void**)&t1,   g_t1);
  cudaGetSymbolAddress((void**)&t2,   g_t2);
  cudaGetSymbolAddress((void**)&qkvb, g_qkvb);
  cudaGetSymbolAddress((void**)&hid,  g_hid);

  cudaFuncSetAttribute(mha_kernel, cudaFuncAttributeMaxDynamicSharedMemorySize, 98304);

  const float isq = 0.07216878364870323f;   // 1/sqrt(192)

  // (1) slots = ln(prev_slots)
  ln_kernel<<<ROWS_S/8, 256>>>(prev_slots, t1, lnq_g, lnq_b, ROWS_S);
  // (2) Wkq = wk^T @ wq  (so qt = slots @ Wkq^T = slots @ wq^T @ wk)
  matmul192_t_kernel<<<192, 192>>>(wk, wq, wkq);
  // (3) qt = alpha * slots @ Wkq^T
  gemm_s<<<dim3(32, 3), 256>>>(t1, nullptr, wkq, nullptr, nullptr, nullptr, nullptr,
                               qt, ROWS_S, 192, 192, 192, isq, 0);
  // (4) Wvo = wo @ wv
  matmul192_kernel<<<192, 192>>>(wo, wvw, wvo);
  // (5) fused LN + inverse cross-attention stream (reads features once; 2 blocks/bt)
  psb_stream_kernel<<<dim3(BT, 2), 512>>>(features, qt, lnkv_g, lnkv_b, y, den);
  // (6) s = ((y0+y1)/(den0+den1)) @ Wvo^T
  gemm_s<<<dim3(32, 3), 256>>>(y, y + (size_t)ROWS_S*DD, wvo, nullptr, nullptr,
                               den, den + ROWS_S, t1, ROWS_S, 192, 192, 192, 1.f, 0);
  // (7-10) time attention
  ln_kernel<<<ROWS_S/8, 256>>>(t1, t2, lnt_g, lnt_b, ROWS_S);
  gemm_s<<<dim3(32, 9), 256>>>(t2, nullptr, t_in_w, t_in_b, nullptr, nullptr, nullptr,
                               qkvb, ROWS_S, 576, 192, 576, 1.f, 0);
  mha_kernel<<<dim3(32, 2), 256, (64*48 + 2*128*48 + 64*128)*4>>>(qkvb, t1, 128, 8);
  gemm_s<<<dim3(32, 3), 256>>>(t1, nullptr, t_out_w, t_out_b, nullptr, nullptr, nullptr,
                               t2, ROWS_S, 192, 192, 192, 1.f, 0);
  // (11) permuted LN replaces transpose + ln
  ln_perm_kernel<<<ROWS_S/8, 256>>>(t2, t1, lno_g, lno_b);
  // (12-14) object attention
  gemm_s<<<dim3(32, 9), 256>>>(t1, nullptr, o_in_w, o_in_b, nullptr, nullptr, nullptr,
                               qkvb, ROWS_S, 576, 192, 576, 1.f, 0);
  mha_kernel<<<dim3(64, 1), 256, (64*48 + 2*64*48 + 64*64)*4>>>(qkvb, t1, 64, 16);
  gemm_s<<<dim3(32, 3), 256>>>(t1, nullptr, o_out_w, o_out_b, nullptr, nullptr, nullptr,
                               t2, ROWS_S, 192, 192, 192, 1.f, 0);
  // (15-17) ln -> FFN(relu) -> proj + residual(prev_slots)
  ln_kernel<<<ROWS_S/8, 256>>>(t2, t1, lnp_g, lnp_b, ROWS_S);
  gemm_s<<<dim3(32, 8), 256>>>(t1, nullptr, w1, b1, nullptr, nullptr, nullptr,
                               hid, ROWS_S, 512, 192, 512, 1.f, 1);
  gemm_s<<<dim3(32, 3), 256>>>(hid, nullptr, w2, b2, prev_slots, nullptr, nullptr,
                               outp, ROWS_S, 192, 512, 192, 1.f, 0);
}

// round 10
// speedup vs baseline: 3.3228x; 1.0419x over previous
#include <cuda_runtime.h>
#include <cstdint>

#define DD 192
#define LL 1024
#define BT 128
#define NS 8
#define ROWS_S   (BT*NS)   /* 1024 */

// ---------------- scratch (device globals; no allocs allowed) ----------------
__device__ float g_qt  [ROWS_S * DD];
__device__ float g_wkq [DD * DD];
__device__ float g_wvo [DD * DD];
__device__ float g_y   [2 * ROWS_S * DD];
__device__ float g_den [2 * ROWS_S];
__device__ float g_t1  [ROWS_S * DD];
__device__ float g_t2  [ROWS_S * DD];
__device__ float g_qkvb[ROWS_S * 576];
__device__ float g_hid [ROWS_S * 512];

// ---------------- packed f32x2 helpers ----------------
__device__ __forceinline__ unsigned long long dup2(float x) {
  unsigned long long r;
  asm("mov.b64 %0, {%1, %1};" : "=l"(r) : "f"(x));
  return r;
}
__device__ __forceinline__ unsigned long long pack2(float lo, float hi) {
  unsigned long long r;
  asm("mov.b64 %0, {%1, %2};" : "=l"(r) : "f"(lo), "f"(hi));
  return r;
}
__device__ __forceinline__ void ffma2(unsigned long long& d, unsigned long long a, unsigned long long b) {
  asm("fma.rn.f32x2 %0, %1, %2, %0;" : "+l"(d) : "l"(a), "l"(b));
}

// ---------------- tiled 192x192 matmul: C = op(A) @ B  (B k-major) ----------------
// grid (6,3), tile 32(M) x 64(N), 256 threads.
// NOTE: As row stride MUST keep 8-byte alignment for the 64-bit smem loads:
// 34 floats = 136 bytes (multiple of 8).  [33 was the R8 misaligned-address bug]
__global__ __launch_bounds__(256)
void mm192_kernel(const float* __restrict__ A, const float* __restrict__ B,
                  float* __restrict__ C, int transA) {
  __shared__ __align__(16) float As[16][34];
  __shared__ __align__(16) float Ws[16][68];
  int t = threadIdx.x;
  int m0 = blockIdx.x * 32, n0 = blockIdx.y * 64;
  int ty = t >> 4, tx = t & 15;
  unsigned long long acc[4] = {};
  int wn = t >> 2, wk = (t & 3) << 2;   // Ws loader coords

  for (int k0 = 0; k0 < DD; k0 += 16) {
    float av[2]; int ak[2], am[2];
#pragma unroll
    for (int h = 0; h < 2; h++) {
      int i = t + h*256;
      ak[h] = i >> 5; am[h] = i & 31;
      av[h] = transA ? A[(size_t)(k0 + ak[h])*DD + m0 + am[h]]
                     : A[(size_t)(m0 + am[h])*DD + k0 + ak[h]];
    }
    float wv[4];
#pragma unroll
    for (int j = 0; j < 4; j++) wv[j] = B[(size_t)(k0 + wk + j)*DD + n0 + wn];
    __syncthreads();
#pragma unroll
    for (int h = 0; h < 2; h++) As[ak[h]][am[h]] = av[h];
#pragma unroll
    for (int j = 0; j < 4; j++) Ws[wk + j][wn] = wv[j];
    __syncthreads();
#pragma unroll
    for (int k = 0; k < 16; k++) {
      unsigned long long ap = *(const unsigned long long*)&As[k][ty*2];
      float4 w4 = *(const float4*)&Ws[k][tx*4];
      ffma2(acc[0], ap, dup2(w4.x));
      ffma2(acc[1], ap, dup2(w4.y));
      ffma2(acc[2], ap, dup2(w4.z));
      ffma2(acc[3], ap, dup2(w4.w));
    }
  }
  int m = m0 + ty*2, n = n0 + tx*4;
  float r0[4], r1[4];
#pragma unroll
  for (int j = 0; j < 4; j++) {
    asm("mov.b64 {%0, %1}, %2;" : "=f"(r0[j]), "=f"(r1[j]) : "l"(acc[j]));
  }
  *(float4*)(C + (size_t)m*DD + n)     = make_float4(r0[0], r0[1], r0[2], r0[3]);
  *(float4*)(C + (size_t)(m+1)*DD + n) = make_float4(r1[0], r1[1], r1[2], r1[3]);
}

// ---------------- fused LN + GEMM: C = alpha*LN(A[perm]) @ W^T [+bias][relu] ----------------
// K fixed = 192. tile 32(M) x 64(N), 256 threads.
__global__ __launch_bounds__(256)
void gemm_ln(const float* __restrict__ A, const float* __restrict__ W,
             const float* __restrict__ bias,
             const float* __restrict__ gamma, const float* __restrict__ beta,
             float* __restrict__ C, int ldc, float alpha, int relu, int perm) {
  __shared__ float Af[32][193];
  __shared__ __align__(16) float Ws[16][68];
  __shared__ float gs[DD], bs[DD];
  int t = threadIdx.x;
  int m0 = blockIdx.x * 32, n0 = blockIdx.y * 64;
  for (int i = t; i < DD; i += 256) { gs[i] = gamma[i]; bs[i] = beta[i]; }
  // load 32 rows (possibly permuted)
  for (int i = t; i < 32*DD; i += 256) {
    int r = i / DD, c = i - r*DD;
    int sr = m0 + r;
    if (perm) { int w = sr; int bb = w >> 7, n = (w >> 4) & 7, tt = w & 15; sr = (bb*16 + tt)*8 + n; }
    Af[r][c] = A[(size_t)sr*DD + c];
  }
  __syncthreads();
  // per-row LN (each warp: 4 rows)
  int wid = t >> 5, lane = t & 31;
#pragma unroll
  for (int i = 0; i < 4; i++) {
    int r = wid*4 + i;
    float s = 0.f, s2 = 0.f;
#pragma unroll
    for (int c0 = 0; c0 < 6; c0++) { float v = Af[r][c0*32 + lane]; s += v; s2 += v*v; }
#pragma unroll
    for (int o = 16; o; o >>= 1) {
      s  += __shfl_xor_sync(0xffffffffu, s,  o);
      s2 += __shfl_xor_sync(0xffffffffu, s2, o);
    }
    float m = s * (1.f/DD);
    float inv = rsqrtf(fmaxf(s2*(1.f/DD) - m*m, 0.f) + 1e-5f);
#pragma unroll
    for (int c0 = 0; c0 < 6; c0++) {
      int c = c0*32 + lane;
      Af[r][c] = (Af[r][c] - m)*inv*gs[c] + bs[c];
    }
  }
  __syncthreads();

  int ty = t >> 4, tx = t & 15;
  int lw = t >> 2, lk = (t & 3) << 2;
  const float* Wp = W + (size_t)(n0 + lw)*DD + lk;
  unsigned long long acc[4] = {};
  for (int k0 = 0; k0 < DD; k0 += 16) {
    float4 w0 = *(const float4*)(Wp + k0);
    __syncthreads();
    Ws[lk+0][lw] = w0.x; Ws[lk+1][lw] = w0.y; Ws[lk+2][lw] = w0.z; Ws[lk+3][lw] = w0.w;
    __syncthreads();
#pragma unroll
    for (int k = 0; k < 16; k++) {
      unsigned long long ap = pack2(Af[ty*2][k0+k], Af[ty*2+1][k0+k]);
      float4 w4 = *(const float4*)&Ws[k][tx*4];
      ffma2(acc[0], ap, dup2(w4.x));
      ffma2(acc[1], ap, dup2(w4.y));
      ffma2(acc[2], ap, dup2(w4.z));
      ffma2(acc[3], ap, dup2(w4.w));
    }
  }
  int m = m0 + ty*2, n = n0 + tx*4;
  float r0[4], r1[4];
#pragma unroll
  for (int j = 0; j < 4; j++) {
    float lo, hi;
    asm("mov.b64 {%0, %1}, %2;" : "=f"(lo), "=f"(hi) : "l"(acc[j]));
    float bv = bias ? bias[n+j] : 0.f;
    float v0 = lo*alpha + bv;
    float v1 = hi*alpha + bv;
    if (relu) { v0 = fmaxf(v0, 0.f); v1 = fmaxf(v1, 0.f); }
    r0[j] = v0; r1[j] = v1;
  }
  *(float4*)(C + (size_t)m*ldc + n)     = make_float4(r0[0], r0[1], r0[2], r0[3]);
  *(float4*)(C + (size_t)(m+1)*ldc + n) = make_float4(r1[0], r1[1], r1[2], r1[3]);
}

// ---------------- fused LN + inverse cross-attention stream (2 blocks per bt) ----------------
__global__ __launch_bounds__(512)
void psb_stream_kernel(const float* __restrict__ features, const float* __restrict__ qt,
                       const float* __restrict__ g, const float* __restrict__ b,
                       float* __restrict__ y, float* __restrict__ den) {
  __shared__ float qs[NS][DD];
  __shared__ float ysum[NS][DD];
  __shared__ float dsum[NS];
  int bt = blockIdx.x;
  int half = blockIdx.y;
  int t = threadIdx.x, wid = t >> 5, lane = t & 31;
  for (int i = t; i < NS*DD; i += 512) {
    qs[i/DD][i%DD] = qt[(size_t)bt*NS*DD + i];
    ysum[i/DD][i%DD] = 0.f;
  }
  if (t < NS) dsum[t] = 0.f;
  float gg[6], bb[6];
#pragma unroll
  for (int j = 0; j < 6; j++) { gg[j] = g[j*32+lane]; bb[j] = b[j*32+lane]; }
  __syncthreads();

  float yacc[NS][6];
  float dacc[NS];
#pragma unroll
  for (int n = 0; n < NS; n++) {
    dacc[n] = 0.f;
#pragma unroll
    for (int j = 0; j < 6; j++) yacc[n][j] = 0.f;
  }

  const float* fb = features + (size_t)bt * LL * DD;
  int s_begin = half * 512 + wid;
  int s_end   = half * 512 + 512;
  float vn[6];
  {
    const float* xr = fb + (size_t)s_begin * DD;
#pragma unroll
    for (int j = 0; j < 6; j++) vn[j] = xr[j*32 + lane];
  }
  for (int s = s_begin; s < s_end; s += 16) {
    float v[6];
#pragma unroll
    for (int j = 0; j < 6; j++) v[j] = vn[j];
    int s2i = s + 16;
    if (s2i < s_end) {
      const float* xr = fb + (size_t)s2i * DD;
#pragma unroll
      for (int j = 0; j < 6; j++) vn[j] = xr[j*32 + lane];
    }
    float sm = 0.f, sq = 0.f;
#pragma unroll
    for (int j = 0; j < 6; j++) { sm += v[j]; sq += v[j]*v[j]; }
#pragma unroll
    for (int o = 16; o; o >>= 1) {
      sm += __shfl_xor_sync(0xffffffffu, sm, o);
      sq += __shfl_xor_sync(0xffffffffu, sq, o);
    }
    float m = sm * (1.f/DD);
    float inv = rsqrtf(fmaxf(sq*(1.f/DD) - m*m, 0.f) + 1e-5f);
#pragma unroll
    for (int j = 0; j < 6; j++) v[j] = (v[j]-m)*inv*gg[j] + bb[j];
    float p[NS];
#pragma unroll
    for (int n = 0; n < NS; n++) {
      float a = 0.f;
#pragma unroll
      for (int j = 0; j < 6; j++) a += v[j] * qs[n][j*32 + lane];
      p[n] = a;
    }
#pragma unroll
    for (int o = 16; o; o >>= 1) {
#pragma unroll
      for (int n = 0; n < NS; n++) p[n] += __shfl_xor_sync(0xffffffffu, p[n], o);
    }
    float mx = p[0];
#pragma unroll
    for (int n = 1; n < NS; n++) mx = fmaxf(mx, p[n]);
    float ssum = 0.f;
#pragma unroll
    for (int n = 0; n < NS; n++) { p[n] = __expf(p[n]-mx); ssum += p[n]; }
    float r = 1.f / ssum;
#pragma unroll
    for (int n = 0; n < NS; n++) {
      float w = p[n] * r;
      dacc[n] += w;
#pragma unroll
      for (int j = 0; j < 6; j++) yacc[n][j] += w * v[j];
    }
  }
#pragma unroll
  for (int n = 0; n < NS; n++)
#pragma unroll
    for (int j = 0; j < 6; j++)
      atomicAdd(&ysum[n][j*32 + lane], yacc[n][j]);
  if (lane == 0)
#pragma unroll
    for (int n = 0; n < NS; n++) atomicAdd(&dsum[n], dacc[n]);
  __syncthreads();
  float* yp = y + (size_t)half * ROWS_S * DD + (size_t)bt*NS*DD;
  for (int i = t; i < NS*DD; i += 512) yp[i] = ysum[i/DD][i%DD];
  if (t < NS) den[half*ROWS_S + bt*NS + t] = dsum[t];
}

// ---------------- small-tile GEMM (no LN): C = alpha*((A[+A2])/rowdiv) @ W^T [+bias][relu][+res] ----------------
__global__ __launch_bounds__(256)
void gemm_s(const float* __restrict__ A, const float* __restrict__ A2,
            const float* __restrict__ W,
            const float* __restrict__ bias, const float* __restrict__ res,
            const float* __restrict__ rowdiv, const float* __restrict__ rowdiv2,
            float* __restrict__ C, int M, int Ncols, int K, int ldc,
            float alpha, int relu) {
  __shared__ __align__(16) float As[16][36];
  __shared__ __align__(16) float Ws[16][68];
  int t = threadIdx.x;
  int m0 = blockIdx.x * 32, n0 = blockIdx.y * 64;
  int lrA = t >> 2, lcA = (t & 3) << 2;
  int lrW = t >> 2, lcW = (t & 3) << 2;
  const float* Ap  = A + (size_t)(m0 + (lrA & 31)) * K + lcA;
  const float* Ap2 = A2 ? A2 + (size_t)(m0 + (lrA & 31)) * K + lcA : nullptr;
  const float* Wp  = W + (size_t)(n0 + lrW) * K + lcW;
  float rsA = 1.f;
  if (rowdiv && t < 128) {
    float d = rowdiv[m0 + lrA];
    if (rowdiv2) d += rowdiv2[m0 + lrA];
    rsA = 1.f / d;
  }
  int ty = t >> 4, tx = t & 15;
  unsigned long long acc[4] = {};

  for (int k0 = 0; k0 < K; k0 += 16) {
    float4 a0 = make_float4(0.f,0.f,0.f,0.f);
    if (t < 128) {
      a0 = *(const float4*)(Ap + k0);
      if (Ap2) {
        float4 a2 = *(const float4*)(Ap2 + k0);
        a0.x += a2.x; a0.y += a2.y; a0.z += a2.z; a0.w += a2.w;
      }
      a0.x *= rsA; a0.y *= rsA; a0.z *= rsA; a0.w *= rsA;
    }
    float4 w0 = *(const float4*)(Wp + k0);
    __syncthreads();
    if (t < 128) {
      As[lcA+0][lrA] = a0.x; As[lcA+1][lrA] = a0.y;
      As[lcA+2][lrA] = a0.z; As[lcA+3][lrA] = a0.w;
    }
    Ws[lcW+0][lrW] = w0.x; Ws[lcW+1][lrW] = w0.y;
    Ws[lcW+2][lrW] = w0.z; Ws[lcW+3][lrW] = w0.w;
    __syncthreads();
#pragma unroll
    for (int k = 0; k < 16; k++) {
      unsigned long long ap = *(const unsigned long long*)&As[k][ty*2];
      float4 wv = *(const float4*)&Ws[k][tx*4];
      ffma2(acc[0], ap, dup2(wv.x));
      ffma2(acc[1], ap, dup2(wv.y));
      ffma2(acc[2], ap, dup2(wv.z));
      ffma2(acc[3], ap, dup2(wv.w));
    }
  }

  int m = m0 + ty*2, n = n0 + tx*4;
  float r0[4], r1[4];
#pragma unroll
  for (int j = 0; j < 4; j++) {
    float lo, hi;
    asm("mov.b64 {%0, %1}, %2;" : "=f"(lo), "=f"(hi) : "l"(acc[j]));
    float bv = bias ? bias[n+j] : 0.f;
    float v0 = lo*alpha + bv;
    float v1 = hi*alpha + bv;
    if (relu) { v0 = fmaxf(v0, 0.f); v1 = fmaxf(v1, 0.f); }
    if (res)  { v0 += res[(size_t)m*Ncols + n+j]; v1 += res[(size_t)(m+1)*Ncols + n+j]; }
    r0[j] = v0; r1[j] = v1;
  }
  *(float4*)(C + (size_t)m*ldc + n)     = make_float4(r0[0], r0[1], r0[2], r0[3]);
  *(float4*)(C + (size_t)(m+1)*ldc + n) = make_float4(r1[0], r1[1], r1[2], r1[3]);
}

// ---------------- MHA core, query-chunked: grid (Bb*4, S/64); nh=4, hd=48 ----------------
__global__ __launch_bounds__(256)
void mha_kernel(const float* __restrict__ qkv, float* __restrict__ out, int S, int Bb) {
  extern __shared__ __align__(16) float smbuf[];
  int b = blockIdx.x >> 2, h = blockIdx.x & 3;
  int i0 = blockIdx.y * 64;
  float* qs = smbuf;
  float* ks = qs + 64*48;
  float* vs = ks + S*48;
  float* sc = vs + S*48;
  int t = threadIdx.x;
  for (int i = t; i < 64*48; i += 256) {
    int s = i / 48, e = i - s*48;
    qs[i] = qkv[((size_t)(i0+s)*Bb + b)*576 + h*48 + e];
  }
  for (int i = t; i < S*48; i += 256) {
    int s = i / 48, e = i - s*48;
    size_t ro = ((size_t)s*Bb + b)*576 + h*48 + e;
    ks[i] = qkv[ro + 192]; vs[i] = qkv[ro + 384];
  }
  __syncthreads();
  const float scale = 0.14433756729740643f;
  for (int idx = t; idx < 64*S; idx += 256) {
    int i = idx / S, s = idx - i*S;
    const float4* qr = (const float4*)(qs + i*48);
    const float4* kr = (const float4*)(ks + s*48);
    float p = 0.f;
#pragma unroll
    for (int j = 0; j < 12; j++) {
      float4 a = qr[j]; float4 kx = kr[j];
      p += a.x*kx.x + a.y*kx.y + a.z*kx.z + a.w*kx.w;
    }
    sc[idx] = p * scale;
  }
  __syncthreads();
  int warp = t >> 5, lane = t & 31;
  for (int i = warp; i < 64; i += 8) {
    float mx = -1e30f;
    for (int s = lane; s < S; s += 32) mx = fmaxf(mx, sc[i*S+s]);
#pragma unroll
    for (int o = 16; o; o >>= 1) mx = fmaxf(mx, __shfl_xor_sync(0xffffffffu, mx, o));
    float sum = 0.f;
    for (int s = lane; s < S; s += 32) { float e = __expf(sc[i*S+s]-mx); sc[i*S+s]=e; sum += e; }
#pragma unroll
    for (int o = 16; o; o >>= 1) sum += __shfl_xor_sync(0xffffffffu, sum, o);
    float r = 1.f / sum;
    for (int s = lane; s < S; s += 32) sc[i*S+s] *= r;
  }
  __syncthreads();
  for (int idx = t; idx < 64*48; idx += 256) {
    int i = idx / 48, e = idx - i*48;
    float acc = 0.f;
#pragma unroll 4
    for (int s = 0; s < S; s++) acc += sc[i*S+s] * vs[s*48+e];
    out[((size_t)(i0+i)*Bb + b)*192 + h*48 + e] = acc;
  }
}

// ---------------- launcher ----------------
extern "C" void kernel_launch(void* const* d_in, const int* in_sizes, int n_in,
                              void* d_out, int out_size) {
  const float* features   = (const float*)d_in[0];
  const float* prev_slots = (const float*)d_in[1];
  const float* lnq_g  = (const float*)d_in[2],  *lnq_b  = (const float*)d_in[3];
  const float* lnkv_g = (const float*)d_in[4],  *lnkv_b = (const float*)d_in[5];
  const float* wq = (const float*)d_in[6],  *wk = (const float*)d_in[7];
  const float* wvw= (const float*)d_in[8],  *wo = (const float*)d_in[9];
  const float* lnt_g  = (const float*)d_in[10], *lnt_b  = (const float*)d_in[11];
  const float* t_in_w = (const float*)d_in[12], *t_in_b = (const float*)d_in[13];
  const float* t_out_w= (const float*)d_in[14], *t_out_b= (const float*)d_in[15];
  const float* lno_g  = (const float*)d_in[16], *lno_b  = (const float*)d_in[17];
  const float* o_in_w = (const float*)d_in[18], *o_in_b = (const float*)d_in[19];
  const float* o_out_w= (const float*)d_in[20], *o_out_b= (const float*)d_in[21];
  const float* lnp_g  = (const float*)d_in[22], *lnp_b  = (const float*)d_in[23];
  const float* w1 = (const float*)d_in[24], *b1 = (const float*)d_in[25];
  const float* w2 = (const float*)d_in[26], *b2 = (const float*)d_in[27];
  float* outp = (float*)d_out;

  float *qt, *wkq, *wvo, *y, *den, *t1, *t2, *qkvb, *hid;
  cudaGetSymbolAddress((void**)&qt,   g_qt);
  cudaGetSymbolAddress((void**)&wkq,  g_wkq);
  cudaGetSymbolAddress((void**)&wvo,  g_wvo);
  cudaGetSymbolAddress((void**)&y,    g_y);
  cudaGetSymbolAddress((void**)&den,  g_den);
  cudaGetSymbolAddress((void**)&t1,   g_t1);
  cudaGetSymbolAddress((void**)&t2,   g_t2);
  cudaGetSymbolAddress((void**)&qkvb, g_qkvb);
  cudaGetSymbolAddress((void**)&hid,  g_hid);

  cudaFuncSetAttribute(mha_kernel, cudaFuncAttributeMaxDynamicSharedMemorySize, 98304);

  const float isq = 0.07216878364870323f;   // 1/sqrt(192)

  // (1) Wkq = wk^T @ wq  (qt = slots @ Wkq^T)
  mm192_kernel<<<dim3(6, 3), 256>>>(wk, wq, wkq, 1);
  // (2) qt = isq * LN(prev_slots;lnq) @ Wkq^T   [fused LN+GEMM]
  gemm_ln<<<dim3(32, 3), 256>>>(prev_slots, wkq, nullptr, lnq_g, lnq_b,
                                qt, DD, isq, 0, 0);
  // (3) Wvo = wo @ wv
  mm192_kernel<<<dim3(6, 3), 256>>>(wo, wvw, wvo, 0);
  // (4) fused LN + inverse cross-attention stream (reads features once; 2 blocks/bt)
  psb_stream_kernel<<<dim3(BT, 2), 512>>>(features, qt, lnkv_g, lnkv_b, y, den);
  // (5) t1 = ((y0+y1)/(den0+den1)) @ Wvo^T
  gemm_s<<<dim3(32, 3), 256>>>(y, y + (size_t)ROWS_S*DD, wvo, nullptr, nullptr,
                               den, den + ROWS_S, t1, ROWS_S, DD, DD, DD, 1.f, 0);
  // (6-8) time attention: fused LN+qkv proj -> mha -> out proj
  gemm_ln<<<dim3(32, 9), 256>>>(t1, t_in_w, t_in_b, lnt_g, lnt_b,
                                qkvb, 576, 1.f, 0, 0);
  mha_kernel<<<dim3(32, 2), 256, (64*48 + 2*128*48 + 64*128)*4>>>(qkvb, t1, 128, 8);
  gemm_s<<<dim3(32, 3), 256>>>(t1, nullptr, t_out_w, t_out_b, nullptr, nullptr, nullptr,
                               t2, ROWS_S, DD, DD, DD, 1.f, 0);
  // (9-11) object attention: fused perm+LN+qkv proj -> mha -> out proj
  gemm_ln<<<dim3(32, 9), 256>>>(t2, o_in_w, o_in_b, lno_g, lno_b,
                                qkvb, 576, 1.f, 0, 1);
  mha_kernel<<<dim3(64, 1), 256, (64*48 + 2*64*48 + 64*64)*4>>>(qkvb, t1, 64, 16);
  gemm_s<<<dim3(32, 3), 256>>>(t1, nullptr, o_out_w, o_out_b, nullptr, nullptr, nullptr,
                               t2, ROWS_S, DD, DD, DD, 1.f, 0);
  // (12-13) fused LN+FFN(relu) -> proj + residual(prev_slots)
  gemm_ln<<<dim3(32, 8), 256>>>(t2, w1, b1, lnp_g, lnp_b,
                                hid, 512, 1.f, 1, 0);
  gemm_s<<<dim3(32, 3), 256>>>(hid, nullptr, w2, b2, prev_slots, nullptr, nullptr,
                               outp, ROWS_S, DD, 512, DD, 1.f, 0);
}

// round 11
// speedup vs baseline: 3.3281x; 1.0016x over previous
#include <cuda_runtime.h>
#include <cstdint>

#define DD 192
#define LL 1024
#define BT 128
#define NS 8
#define ROWS_S   (BT*NS)   /* 1024 */
#define NPART 4

typedef unsigned long long ull;

// ---------------- scratch (device globals; no allocs allowed) ----------------
__device__ float g_qt  [ROWS_S * DD];
__device__ float g_wkq [DD * DD];
__device__ float g_wvo [DD * DD];
__device__ float g_y   [NPART * ROWS_S * DD];
__device__ float g_den [NPART * ROWS_S];
__device__ float g_t1  [ROWS_S * DD];
__device__ float g_t2  [ROWS_S * DD];
__device__ float g_qkvb[ROWS_S * 576];
__device__ float g_hid [ROWS_S * 512];

// ---------------- packed f32x2 helpers ----------------
__device__ __forceinline__ ull dup2(float x) {
  ull r; asm("mov.b64 %0, {%1, %1};" : "=l"(r) : "f"(x)); return r;
}
__device__ __forceinline__ ull pack2(float lo, float hi) {
  ull r; asm("mov.b64 %0, {%1, %2};" : "=l"(r) : "f"(lo), "f"(hi)); return r;
}
__device__ __forceinline__ void unpack2(ull v, float& lo, float& hi) {
  asm("mov.b64 {%0, %1}, %2;" : "=f"(lo), "=f"(hi) : "l"(v));
}
__device__ __forceinline__ void ffma2(ull& d, ull a, ull b) {
  asm("fma.rn.f32x2 %0, %1, %2, %0;" : "+l"(d) : "l"(a), "l"(b));
}
__device__ __forceinline__ ull add2(ull a, ull b) {
  ull r; asm("add.rn.f32x2 %0, %1, %2;" : "=l"(r) : "l"(a), "l"(b)); return r;
}

// ---------------- tiled 192x192 matmul: C = op(A) @ B  (B k-major) ----------------
__global__ __launch_bounds__(256)
void mm192_kernel(const float* __restrict__ A, const float* __restrict__ B,
                  float* __restrict__ C, int transA) {
  __shared__ __align__(16) float As[16][34];   // 34: keep 8B alignment for 64-bit LDS
  __shared__ __align__(16) float Ws[16][68];
  int t = threadIdx.x;
  int m0 = blockIdx.x * 32, n0 = blockIdx.y * 64;
  int ty = t >> 4, tx = t & 15;
  ull acc[4] = {};
  int wn = t >> 2, wk = (t & 3) << 2;

  for (int k0 = 0; k0 < DD; k0 += 16) {
    float av[2]; int ak[2], am[2];
#pragma unroll
    for (int h = 0; h < 2; h++) {
      int i = t + h*256;
      ak[h] = i >> 5; am[h] = i & 31;
      av[h] = transA ? A[(size_t)(k0 + ak[h])*DD + m0 + am[h]]
                     : A[(size_t)(m0 + am[h])*DD + k0 + ak[h]];
    }
    float wv[4];
#pragma unroll
    for (int j = 0; j < 4; j++) wv[j] = B[(size_t)(k0 + wk + j)*DD + n0 + wn];
    __syncthreads();
#pragma unroll
    for (int h = 0; h < 2; h++) As[ak[h]][am[h]] = av[h];
#pragma unroll
    for (int j = 0; j < 4; j++) Ws[wk + j][wn] = wv[j];
    __syncthreads();
#pragma unroll
    for (int k = 0; k < 16; k++) {
      ull ap = *(const ull*)&As[k][ty*2];
      float4 w4 = *(const float4*)&Ws[k][tx*4];
      ffma2(acc[0], ap, dup2(w4.x));
      ffma2(acc[1], ap, dup2(w4.y));
      ffma2(acc[2], ap, dup2(w4.z));
      ffma2(acc[3], ap, dup2(w4.w));
    }
  }
  int m = m0 + ty*2, n = n0 + tx*4;
  float r0[4], r1[4];
#pragma unroll
  for (int j = 0; j < 4; j++) unpack2(acc[j], r0[j], r1[j]);
  *(float4*)(C + (size_t)m*DD + n)     = make_float4(r0[0], r0[1], r0[2], r0[3]);
  *(float4*)(C + (size_t)(m+1)*DD + n) = make_float4(r1[0], r1[1], r1[2], r1[3]);
}

// ---------------- fused LN + GEMM: C = alpha*LN(A[perm]) @ W^T [+bias][relu] ----------------
__global__ __launch_bounds__(256)
void gemm_ln(const float* __restrict__ A, const float* __restrict__ W,
             const float* __restrict__ bias,
             const float* __restrict__ gamma, const float* __restrict__ beta,
             float* __restrict__ C, int ldc, float alpha, int relu, int perm) {
  __shared__ float Af[32][193];
  __shared__ __align__(16) float Ws[16][68];
  __shared__ float gs[DD], bs[DD];
  int t = threadIdx.x;
  int m0 = blockIdx.x * 32, n0 = blockIdx.y * 64;
  for (int i = t; i < DD; i += 256) { gs[i] = gamma[i]; bs[i] = beta[i]; }
  for (int i = t; i < 32*DD; i += 256) {
    int r = i / DD, c = i - r*DD;
    int sr = m0 + r;
    if (perm) { int w = sr; int bb = w >> 7, n = (w >> 4) & 7, tt = w & 15; sr = (bb*16 + tt)*8 + n; }
    Af[r][c] = A[(size_t)sr*DD + c];
  }
  __syncthreads();
  int wid = t >> 5, lane = t & 31;
#pragma unroll
  for (int i = 0; i < 4; i++) {
    int r = wid*4 + i;
    float s = 0.f, s2 = 0.f;
#pragma unroll
    for (int c0 = 0; c0 < 6; c0++) { float v = Af[r][c0*32 + lane]; s += v; s2 += v*v; }
#pragma unroll
    for (int o = 16; o; o >>= 1) {
      s  += __shfl_xor_sync(0xffffffffu, s,  o);
      s2 += __shfl_xor_sync(0xffffffffu, s2, o);
    }
    float m = s * (1.f/DD);
    float inv = rsqrtf(fmaxf(s2*(1.f/DD) - m*m, 0.f) + 1e-5f);
#pragma unroll
    for (int c0 = 0; c0 < 6; c0++) {
      int c = c0*32 + lane;
      Af[r][c] = (Af[r][c] - m)*inv*gs[c] + bs[c];
    }
  }
  __syncthreads();

  int ty = t >> 4, tx = t & 15;
  int lw = t >> 2, lk = (t & 3) << 2;
  const float* Wp = W + (size_t)(n0 + lw)*DD + lk;
  ull acc[4] = {};
  for (int k0 = 0; k0 < DD; k0 += 16) {
    float4 w0 = *(const float4*)(Wp + k0);
    __syncthreads();
    Ws[lk+0][lw] = w0.x; Ws[lk+1][lw] = w0.y; Ws[lk+2][lw] = w0.z; Ws[lk+3][lw] = w0.w;
    __syncthreads();
#pragma unroll
    for (int k = 0; k < 16; k++) {
      ull ap = pack2(Af[ty*2][k0+k], Af[ty*2+1][k0+k]);
      float4 w4 = *(const float4*)&Ws[k][tx*4];
      ffma2(acc[0], ap, dup2(w4.x));
      ffma2(acc[1], ap, dup2(w4.y));
      ffma2(acc[2], ap, dup2(w4.z));
      ffma2(acc[3], ap, dup2(w4.w));
    }
  }
  int m = m0 + ty*2, n = n0 + tx*4;
  float r0[4], r1[4];
#pragma unroll
  for (int j = 0; j < 4; j++) {
    float lo, hi; unpack2(acc[j], lo, hi);
    float bv = bias ? bias[n+j] : 0.f;
    float v0 = lo*alpha + bv;
    float v1 = hi*alpha + bv;
    if (relu) { v0 = fmaxf(v0, 0.f); v1 = fmaxf(v1, 0.f); }
    r0[j] = v0; r1[j] = v1;
  }
  *(float4*)(C + (size_t)m*ldc + n)     = make_float4(r0[0], r0[1], r0[2], r0[3]);
  *(float4*)(C + (size_t)(m+1)*ldc + n) = make_float4(r1[0], r1[1], r1[2], r1[3]);
}

// ---------------- fused LN + inverse cross-attention stream (4 blocks per bt) ----------------
// Slot-pair packed f32x2 arithmetic: dots/accumulates at half instruction count.
__global__ __launch_bounds__(512)
void psb_stream_kernel(const float* __restrict__ features, const float* __restrict__ qt,
                       const float* __restrict__ g, const float* __restrict__ b,
                       float* __restrict__ y, float* __restrict__ den) {
  __shared__ ull   qsp[4*DD];     // packed (slot2m, slot2m+1) per dim
  __shared__ float ysum[NS*DD];
  __shared__ float dsum[NS];
  int bt = blockIdx.x, q4 = blockIdx.y;
  int t = threadIdx.x, wid = t >> 5, lane = t & 31;
  const float* qtb = qt + (size_t)bt*NS*DD;
  for (int i = t; i < 4*DD; i += 512) {
    int m = i / DD, c = i - m*DD;
    qsp[m*DD + c] = pack2(qtb[(2*m)*DD + c], qtb[(2*m+1)*DD + c]);
  }
  for (int i = t; i < NS*DD; i += 512) ysum[i] = 0.f;
  if (t < NS) dsum[t] = 0.f;
  float gg[6], bb[6];
#pragma unroll
  for (int j = 0; j < 6; j++) { gg[j] = g[j*32+lane]; bb[j] = b[j*32+lane]; }
  __syncthreads();

  ull yacc[4][6] = {};
  ull dden[4] = {};

  const float* fb = features + (size_t)bt * LL * DD;
  int s_begin = q4*256 + wid;
  int s_end   = q4*256 + 256;
  float vn[6];
  {
    const float* xr = fb + (size_t)s_begin * DD;
#pragma unroll
    for (int j = 0; j < 6; j++) vn[j] = xr[j*32 + lane];
  }
  for (int s = s_begin; s < s_end; s += 16) {
    float v[6];
#pragma unroll
    for (int j = 0; j < 6; j++) v[j] = vn[j];
    int s2i = s + 16;
    if (s2i < s_end) {
      const float* xr = fb + (size_t)s2i * DD;
#pragma unroll
      for (int j = 0; j < 6; j++) vn[j] = xr[j*32 + lane];
    }
    // LN
    float sm = 0.f, sq = 0.f;
#pragma unroll
    for (int j = 0; j < 6; j++) { sm += v[j]; sq += v[j]*v[j]; }
#pragma unroll
    for (int o = 16; o; o >>= 1) {
      sm += __shfl_xor_sync(0xffffffffu, sm, o);
      sq += __shfl_xor_sync(0xffffffffu, sq, o);
    }
    float m = sm * (1.f/DD);
    float inv = rsqrtf(fmaxf(sq*(1.f/DD) - m*m, 0.f) + 1e-5f);
#pragma unroll
    for (int j = 0; j < 6; j++) v[j] = (v[j]-m)*inv*gg[j] + bb[j];
    // packed dots: pp[m] = (p[2m], p[2m+1])
    ull pp[4] = {};
#pragma unroll
    for (int mI = 0; mI < 4; mI++) {
#pragma unroll
      for (int j = 0; j < 6; j++)
        ffma2(pp[mI], dup2(v[j]), qsp[mI*DD + j*32 + lane]);
    }
#pragma unroll
    for (int o = 16; o; o >>= 1) {
#pragma unroll
      for (int mI = 0; mI < 4; mI++)
        pp[mI] = add2(pp[mI], __shfl_xor_sync(0xffffffffu, pp[mI], o));
    }
    float p[NS];
#pragma unroll
    for (int mI = 0; mI < 4; mI++) unpack2(pp[mI], p[2*mI], p[2*mI+1]);
    // softmax over 8 slots (local)
    float mx = p[0];
#pragma unroll
    for (int n = 1; n < NS; n++) mx = fmaxf(mx, p[n]);
    float ssum = 0.f;
#pragma unroll
    for (int n = 0; n < NS; n++) { p[n] = __expf(p[n]-mx); ssum += p[n]; }
    float r = 1.f / ssum;
    ull wp[4];
#pragma unroll
    for (int mI = 0; mI < 4; mI++) {
      wp[mI] = pack2(p[2*mI]*r, p[2*mI+1]*r);
      dden[mI] = add2(dden[mI], wp[mI]);
#pragma unroll
      for (int j = 0; j < 6; j++) ffma2(yacc[mI][j], dup2(v[j]), wp[mI]);
    }
  }
  // merge across warps
#pragma unroll
  for (int mI = 0; mI < 4; mI++) {
#pragma unroll
    for (int j = 0; j < 6; j++) {
      float lo, hi; unpack2(yacc[mI][j], lo, hi);
      atomicAdd(&ysum[(2*mI)*DD + j*32 + lane], lo);
      atomicAdd(&ysum[(2*mI+1)*DD + j*32 + lane], hi);
    }
  }
  if (lane == 0) {
#pragma unroll
    for (int mI = 0; mI < 4; mI++) {
      float lo, hi; unpack2(dden[mI], lo, hi);
      atomicAdd(&dsum[2*mI], lo);
      atomicAdd(&dsum[2*mI+1], hi);
    }
  }
  __syncthreads();
  float* yp = y + (size_t)q4 * ROWS_S * DD + (size_t)bt*NS*DD;
  for (int i = t; i < NS*DD; i += 512) yp[i] = ysum[i];
  if (t < NS) den[q4*ROWS_S + bt*NS + t] = dsum[t];
}

// ---------------- small-tile GEMM: C = alpha*((sum_p A_p)/sum_p rowdiv_p) @ W^T [+bias][relu][+res] ----------------
__global__ __launch_bounds__(256)
void gemm_s(const float* __restrict__ A, const float* __restrict__ W,
            const float* __restrict__ bias, const float* __restrict__ res,
            const float* __restrict__ rowdiv,
            float* __restrict__ C, int M, int Ncols, int K, int ldc,
            float alpha, int relu, int nacc) {
  __shared__ __align__(16) float As[16][36];
  __shared__ __align__(16) float Ws[16][68];
  int t = threadIdx.x;
  int m0 = blockIdx.x * 32, n0 = blockIdx.y * 64;
  int lrA = t >> 2, lcA = (t & 3) << 2;
  int lrW = t >> 2, lcW = (t & 3) << 2;
  const float* Ap = A + (size_t)(m0 + (lrA & 31)) * K + lcA;
  const float* Wp = W + (size_t)(n0 + lrW) * K + lcW;
  float rsA = 1.f;
  if (rowdiv && t < 128) {
    float d = 0.f;
    for (int p = 0; p < nacc; p++) d += rowdiv[p*ROWS_S + m0 + lrA];
    rsA = 1.f / d;
  }
  int ty = t >> 4, tx = t & 15;
  ull acc[4] = {};

  for (int k0 = 0; k0 < K; k0 += 16) {
    float4 a0 = make_float4(0.f,0.f,0.f,0.f);
    if (t < 128) {
      a0 = *(const float4*)(Ap + k0);
      for (int p = 1; p < nacc; p++) {
        float4 a2 = *(const float4*)(Ap + (size_t)p*ROWS_S*DD + k0);
        a0.x += a2.x; a0.y += a2.y; a0.z += a2.z; a0.w += a2.w;
      }
      a0.x *= rsA; a0.y *= rsA; a0.z *= rsA; a0.w *= rsA;
    }
    float4 w0 = *(const float4*)(Wp + k0);
    __syncthreads();
    if (t < 128) {
      As[lcA+0][lrA] = a0.x; As[lcA+1][lrA] = a0.y;
      As[lcA+2][lrA] = a0.z; As[lcA+3][lrA] = a0.w;
    }
    Ws[lcW+0][lrW] = w0.x; Ws[lcW+1][lrW] = w0.y;
    Ws[lcW+2][lrW] = w0.z; Ws[lcW+3][lrW] = w0.w;
    __syncthreads();
#pragma unroll
    for (int k = 0; k < 16; k++) {
      ull ap = *(const ull*)&As[k][ty*2];
      float4 wv = *(const float4*)&Ws[k][tx*4];
      ffma2(acc[0], ap, dup2(wv.x));
      ffma2(acc[1], ap, dup2(wv.y));
      ffma2(acc[2], ap, dup2(wv.z));
      ffma2(acc[3], ap, dup2(wv.w));
    }
  }

  int m = m0 + ty*2, n = n0 + tx*4;
  float r0[4], r1[4];
#pragma unroll
  for (int j = 0; j < 4; j++) {
    float lo, hi; unpack2(acc[j], lo, hi);
    float bv = bias ? bias[n+j] : 0.f;
    float v0 = lo*alpha + bv;
    float v1 = hi*alpha + bv;
    if (relu) { v0 = fmaxf(v0, 0.f); v1 = fmaxf(v1, 0.f); }
    if (res)  { v0 += res[(size_t)m*Ncols + n+j]; v1 += res[(size_t)(m+1)*Ncols + n+j]; }
    r0[j] = v0; r1[j] = v1;
  }
  *(float4*)(C + (size_t)m*ldc + n)     = make_float4(r0[0], r0[1], r0[2], r0[3]);
  *(float4*)(C + (size_t)(m+1)*ldc + n) = make_float4(r1[0], r1[1], r1[2], r1[3]);
}

// ---------------- MHA core, query-chunked: grid (Bb*4, S/64); nh=4, hd=48 ----------------
__global__ __launch_bounds__(256)
void mha_kernel(const float* __restrict__ qkv, float* __restrict__ out, int S, int Bb) {
  extern __shared__ __align__(16) float smbuf[];
  int b = blockIdx.x >> 2, h = blockIdx.x & 3;
  int i0 = blockIdx.y * 64;
  float* qs = smbuf;
  float* ks = qs + 64*48;
  float* vs = ks + S*48;
  float* sc = vs + S*48;
  int t = threadIdx.x;
  for (int i = t; i < 64*48; i += 256) {
    int s = i / 48, e = i - s*48;
    qs[i] = qkv[((size_t)(i0+s)*Bb + b)*576 + h*48 + e];
  }
  for (int i = t; i < S*48; i += 256) {
    int s = i / 48, e = i - s*48;
    size_t ro = ((size_t)s*Bb + b)*576 + h*48 + e;
    ks[i] = qkv[ro + 192]; vs[i] = qkv[ro + 384];
  }
  __syncthreads();
  const float scale = 0.14433756729740643f;
  // QK^T with packed FFMA2
  for (int idx = t; idx < 64*S; idx += 256) {
    int i = idx / S, s = idx - i*S;
    const float4* qr = (const float4*)(qs + i*48);
    const float4* kr = (const float4*)(ks + s*48);
    ull pp = 0;
#pragma unroll
    for (int j = 0; j < 12; j++) {
      float4 a = qr[j]; float4 kx = kr[j];
      ffma2(pp, pack2(a.x, a.y), pack2(kx.x, kx.y));
      ffma2(pp, pack2(a.z, a.w), pack2(kx.z, kx.w));
    }
    float lo, hi; unpack2(pp, lo, hi);
    sc[idx] = (lo + hi) * scale;
  }
  __syncthreads();
  int warp = t >> 5, lane = t & 31;
  for (int i = warp; i < 64; i += 8) {
    float mx = -1e30f;
    for (int s = lane; s < S; s += 32) mx = fmaxf(mx, sc[i*S+s]);
#pragma unroll
    for (int o = 16; o; o >>= 1) mx = fmaxf(mx, __shfl_xor_sync(0xffffffffu, mx, o));
    float sum = 0.f;
    for (int s = lane; s < S; s += 32) { float e = __expf(sc[i*S+s]-mx); sc[i*S+s]=e; sum += e; }
#pragma unroll
    for (int o = 16; o; o >>= 1) sum += __shfl_xor_sync(0xffffffffu, sum, o);
    float r = 1.f / sum;
    for (int s = lane; s < S; s += 32) sc[i*S+s] *= r;
  }
  __syncthreads();
  // AV, float4-vectorized with packed FFMA2: item = (query i, 4-col group e4)
  for (int idx = t; idx < 64*12; idx += 256) {
    int i = idx / 12, e4 = idx - i*12;
    ull a0 = 0, a1 = 0;
    const float* vcol = vs + e4*4;
#pragma unroll 4
    for (int s = 0; s < S; s++) {
      ull w2 = dup2(sc[i*S + s]);
      float4 vv = *(const float4*)(vcol + s*48);
      ffma2(a0, w2, pack2(vv.x, vv.y));
      ffma2(a1, w2, pack2(vv.z, vv.w));
    }
    float o0, o1, o2, o3;
    unpack2(a0, o0, o1); unpack2(a1, o2, o3);
    *(float4*)(out + ((size_t)(i0+i)*Bb + b)*192 + h*48 + e4*4) = make_float4(o0, o1, o2, o3);
  }
}

// ---------------- launcher ----------------
extern "C" void kernel_launch(void* const* d_in, const int* in_sizes, int n_in,
                              void* d_out, int out_size) {
  const float* features   = (const float*)d_in[0];
  const float* prev_slots = (const float*)d_in[1];
  const float* lnq_g  = (const float*)d_in[2],  *lnq_b  = (const float*)d_in[3];
  const float* lnkv_g = (const float*)d_in[4],  *lnkv_b = (const float*)d_in[5];
  const float* wq = (const float*)d_in[6],  *wk = (const float*)d_in[7];
  const float* wvw= (const float*)d_in[8],  *wo = (const float*)d_in[9];
  const float* lnt_g  = (const float*)d_in[10], *lnt_b  = (const float*)d_in[11];
  const float* t_in_w = (const float*)d_in[12], *t_in_b = (const float*)d_in[13];
  const float* t_out_w= (const float*)d_in[14], *t_out_b= (const float*)d_in[15];
  const float* lno_g  = (const float*)d_in[16], *lno_b  = (const float*)d_in[17];
  const float* o_in_w = (const float*)d_in[18], *o_in_b = (const float*)d_in[19];
  const float* o_out_w= (const float*)d_in[20], *o_out_b= (const float*)d_in[21];
  const float* lnp_g  = (const float*)d_in[22], *lnp_b  = (const float*)d_in[23];
  const float* w1 = (const float*)d_in[24], *b1 = (const float*)d_in[25];
  const float* w2 = (const float*)d_in[26], *b2 = (const float*)d_in[27];
  float* outp = (float*)d_out;

  float *qt, *wkq, *wvo, *y, *den, *t1, *t2, *qkvb, *hid;
  cudaGetSymbolAddress((void**)&qt,   g_qt);
  cudaGetSymbolAddress((void**)&wkq,  g_wkq);
  cudaGetSymbolAddress((void**)&wvo,  g_wvo);
  cudaGetSymbolAddress((void**)&y,    g_y);
  cudaGetSymbolAddress((void**)&den,  g_den);
  cudaGetSymbolAddress((void**)&t1,   g_t1);
  cudaGetSymbolAddress((void**)&t2,   g_t2);
  cudaGetSymbolAddress((void**)&qkvb, g_qkvb);
  cudaGetSymbolAddress((void**)&hid,  g_hid);

  cudaFuncSetAttribute(mha_kernel, cudaFuncAttributeMaxDynamicSharedMemorySize, 98304);

  const float isq = 0.07216878364870323f;   // 1/sqrt(192)

  // (1) Wkq = wk^T @ wq
  mm192_kernel<<<dim3(6, 3), 256>>>(wk, wq, wkq, 1);
  // (2) qt = isq * LN(prev_slots;lnq) @ Wkq^T
  gemm_ln<<<dim3(32, 3), 256>>>(prev_slots, wkq, nullptr, lnq_g, lnq_b,
                                qt, DD, isq, 0, 0);
  // (3) Wvo = wo @ wv
  mm192_kernel<<<dim3(6, 3), 256>>>(wo, wvw, wvo, 0);
  // (4) fused LN + inverse cross-attention stream (4 key-slices per bt)
  psb_stream_kernel<<<dim3(BT, NPART), 512>>>(features, qt, lnkv_g, lnkv_b, y, den);
  // (5) t1 = (sum_p y_p / sum_p den_p) @ Wvo^T
  gemm_s<<<dim3(32, 3), 256>>>(y, wvo, nullptr, nullptr, den,
                               t1, ROWS_S, DD, DD, DD, 1.f, 0, NPART);
  // (6-8) time attention
  gemm_ln<<<dim3(32, 9), 256>>>(t1, t_in_w, t_in_b, lnt_g, lnt_b,
                                qkvb, 576, 1.f, 0, 0);
  mha_kernel<<<dim3(32, 2), 256, (64*48 + 2*128*48 + 64*128)*4>>>(qkvb, t1, 128, 8);
  gemm_s<<<dim3(32, 3), 256>>>(t1, t_out_w, t_out_b, nullptr, nullptr,
                               t2, ROWS_S, DD, DD, DD, 1.f, 0, 1);
  // (9-11) object attention (perm fused into LN+GEMM)
  gemm_ln<<<dim3(32, 9), 256>>>(t2, o_in_w, o_in_b, lno_g, lno_b,
                                qkvb, 576, 1.f, 0, 1);
  mha_kernel<<<dim3(64, 1), 256, (64*48 + 2*64*48 + 64*64)*4>>>(qkvb, t1, 64, 16);
  gemm_s<<<dim3(32, 3), 256>>>(t1, o_out_w, o_out_b, nullptr, nullptr,
                               t2, ROWS_S, DD, DD, DD, 1.f, 0, 1);
  // (12-13) fused LN+FFN(relu) -> proj + residual(prev_slots)
  gemm_ln<<<dim3(32, 8), 256>>>(t2, w1, b1, lnp_g, lnp_b,
                                hid, 512, 1.f, 1, 0);
  gemm_s<<<dim3(32, 3), 256>>>(hid, w2, b2, prev_slots, nullptr,
                               outp, ROWS_S, DD, 512, DD, 1.f, 0, 1);
}

// round 12
// speedup vs baseline: 3.4884x; 1.0482x over previous
#include <cuda_runtime.h>
#include <cstdint>

#define DD 192
#define LL 1024
#define BT 128
#define NS 8
#define ROWS_S   (BT*NS)   /* 1024 */
#define NPART 4

typedef unsigned long long ull;

// ---------------- scratch (device globals; no allocs allowed) ----------------
__device__ float g_qt  [ROWS_S * DD];
__device__ float g_wkq [DD * DD];
__device__ float g_wvo [DD * DD];
__device__ float g_y   [NPART * ROWS_S * DD];
__device__ float g_den [NPART * ROWS_S];
__device__ float g_t1  [ROWS_S * DD];
__device__ float g_t2  [ROWS_S * DD];
__device__ float g_qkvb[ROWS_S * 576];
__device__ float g_hid [ROWS_S * 512];

// ---------------- packed f32x2 helpers ----------------
__device__ __forceinline__ ull dup2(float x) {
  ull r; asm("mov.b64 %0, {%1, %1};" : "=l"(r) : "f"(x)); return r;
}
__device__ __forceinline__ ull pack2(float lo, float hi) {
  ull r; asm("mov.b64 %0, {%1, %2};" : "=l"(r) : "f"(lo), "f"(hi)); return r;
}
__device__ __forceinline__ void unpack2(ull v, float& lo, float& hi) {
  asm("mov.b64 {%0, %1}, %2;" : "=f"(lo), "=f"(hi) : "l"(v));
}
__device__ __forceinline__ void ffma2(ull& d, ull a, ull b) {
  asm("fma.rn.f32x2 %0, %1, %2, %0;" : "+l"(d) : "l"(a), "l"(b));
}
__device__ __forceinline__ ull add2(ull a, ull b) {
  ull r; asm("add.rn.f32x2 %0, %1, %2;" : "=l"(r) : "l"(a), "l"(b)); return r;
}
__device__ __forceinline__ ull mul2(ull a, ull b) {
  ull r; asm("mul.rn.f32x2 %0, %1, %2;" : "=l"(r) : "l"(a), "l"(b)); return r;
}

// ---------------- tiled 192x192 matmul: C = op(A) @ B  (B k-major) ----------------
__global__ __launch_bounds__(256)
void mm192_kernel(const float* __restrict__ A, const float* __restrict__ B,
                  float* __restrict__ C, int transA) {
  __shared__ __align__(16) float As[16][34];   // 34: keep 8B alignment for 64-bit LDS
  __shared__ __align__(16) float Ws[16][68];
  int t = threadIdx.x;
  int m0 = blockIdx.x * 32, n0 = blockIdx.y * 64;
  int ty = t >> 4, tx = t & 15;
  ull acc[4] = {};
  int wn = t >> 2, wk = (t & 3) << 2;

  for (int k0 = 0; k0 < DD; k0 += 16) {
    float av[2]; int ak[2], am[2];
#pragma unroll
    for (int h = 0; h < 2; h++) {
      int i = t + h*256;
      ak[h] = i >> 5; am[h] = i & 31;
      av[h] = transA ? A[(size_t)(k0 + ak[h])*DD + m0 + am[h]]
                     : A[(size_t)(m0 + am[h])*DD + k0 + ak[h]];
    }
    float wv[4];
#pragma unroll
    for (int j = 0; j < 4; j++) wv[j] = B[(size_t)(k0 + wk + j)*DD + n0 + wn];
    __syncthreads();
#pragma unroll
    for (int h = 0; h < 2; h++) As[ak[h]][am[h]] = av[h];
#pragma unroll
    for (int j = 0; j < 4; j++) Ws[wk + j][wn] = wv[j];
    __syncthreads();
#pragma unroll
    for (int k = 0; k < 16; k++) {
      ull ap = *(const ull*)&As[k][ty*2];
      float4 w4 = *(const float4*)&Ws[k][tx*4];
      ffma2(acc[0], ap, dup2(w4.x));
      ffma2(acc[1], ap, dup2(w4.y));
      ffma2(acc[2], ap, dup2(w4.z));
      ffma2(acc[3], ap, dup2(w4.w));
    }
  }
  int m = m0 + ty*2, n = n0 + tx*4;
  float r0[4], r1[4];
#pragma unroll
  for (int j = 0; j < 4; j++) unpack2(acc[j], r0[j], r1[j]);
  *(float4*)(C + (size_t)m*DD + n)     = make_float4(r0[0], r0[1], r0[2], r0[3]);
  *(float4*)(C + (size_t)(m+1)*DD + n) = make_float4(r1[0], r1[1], r1[2], r1[3]);
}

// ---------------- fused LN + GEMM: C = alpha*LN(A[perm]) @ W^T [+bias][relu] ----------------
__global__ __launch_bounds__(256)
void gemm_ln(const float* __restrict__ A, const float* __restrict__ W,
             const float* __restrict__ bias,
             const float* __restrict__ gamma, const float* __restrict__ beta,
             float* __restrict__ C, int ldc, float alpha, int relu, int perm) {
  __shared__ float Af[32][193];
  __shared__ __align__(16) float Ws[16][68];
  __shared__ float gs[DD], bs[DD];
  int t = threadIdx.x;
  int m0 = blockIdx.x * 32, n0 = blockIdx.y * 64;
  for (int i = t; i < DD; i += 256) { gs[i] = gamma[i]; bs[i] = beta[i]; }
  for (int i = t; i < 32*DD; i += 256) {
    int r = i / DD, c = i - r*DD;
    int sr = m0 + r;
    if (perm) { int w = sr; int bb = w >> 7, n = (w >> 4) & 7, tt = w & 15; sr = (bb*16 + tt)*8 + n; }
    Af[r][c] = A[(size_t)sr*DD + c];
  }
  __syncthreads();
  int wid = t >> 5, lane = t & 31;
#pragma unroll
  for (int i = 0; i < 4; i++) {
    int r = wid*4 + i;
    float s = 0.f, s2 = 0.f;
#pragma unroll
    for (int c0 = 0; c0 < 6; c0++) { float v = Af[r][c0*32 + lane]; s += v; s2 += v*v; }
#pragma unroll
    for (int o = 16; o; o >>= 1) {
      s  += __shfl_xor_sync(0xffffffffu, s,  o);
      s2 += __shfl_xor_sync(0xffffffffu, s2, o);
    }
    float m = s * (1.f/DD);
    float inv = rsqrtf(fmaxf(s2*(1.f/DD) - m*m, 0.f) + 1e-5f);
#pragma unroll
    for (int c0 = 0; c0 < 6; c0++) {
      int c = c0*32 + lane;
      Af[r][c] = (Af[r][c] - m)*inv*gs[c] + bs[c];
    }
  }
  __syncthreads();

  int ty = t >> 4, tx = t & 15;
  int lw = t >> 2, lk = (t & 3) << 2;
  const float* Wp = W + (size_t)(n0 + lw)*DD + lk;
  ull acc[4] = {};
  for (int k0 = 0; k0 < DD; k0 += 16) {
    float4 w0 = *(const float4*)(Wp + k0);
    __syncthreads();
    Ws[lk+0][lw] = w0.x; Ws[lk+1][lw] = w0.y; Ws[lk+2][lw] = w0.z; Ws[lk+3][lw] = w0.w;
    __syncthreads();
#pragma unroll
    for (int k = 0; k < 16; k++) {
      ull ap = pack2(Af[ty*2][k0+k], Af[ty*2+1][k0+k]);
      float4 w4 = *(const float4*)&Ws[k][tx*4];
      ffma2(acc[0], ap, dup2(w4.x));
      ffma2(acc[1], ap, dup2(w4.y));
      ffma2(acc[2], ap, dup2(w4.z));
      ffma2(acc[3], ap, dup2(w4.w));
    }
  }
  int m = m0 + ty*2, n = n0 + tx*4;
  float r0[4], r1[4];
#pragma unroll
  for (int j = 0; j < 4; j++) {
    float lo, hi; unpack2(acc[j], lo, hi);
    float bv = bias ? bias[n+j] : 0.f;
    float v0 = lo*alpha + bv;
    float v1 = hi*alpha + bv;
    if (relu) { v0 = fmaxf(v0, 0.f); v1 = fmaxf(v1, 0.f); }
    r0[j] = v0; r1[j] = v1;
  }
  *(float4*)(C + (size_t)m*ldc + n)     = make_float4(r0[0], r0[1], r0[2], r0[3]);
  *(float4*)(C + (size_t)(m+1)*ldc + n) = make_float4(r1[0], r1[1], r1[2], r1[3]);
}

// ---------------- fused LN + inverse cross-attention stream (4 blocks per bt) ----------------
// Single merged shuffle-reduce round: (sum, sumsq) packed + 4 packed raw-v dots.
// LN folded algebraically:  p_n = inv*<v, g.q_n> - inv*mean*S1_n + B_n
// Deferred output transform: y_n = g.(YA_n - C_n) + b*DEN_n  (linear -> per-partial OK)
__global__ __launch_bounds__(512)
void psb_stream_kernel(const float* __restrict__ features, const float* __restrict__ qt,
                       const float* __restrict__ g, const float* __restrict__ b,
                       float* __restrict__ y, float* __restrict__ den) {
  __shared__ ull   qgp[4*DD];            // packed (g*q_{2m}, g*q_{2m+1}) per dim
  __shared__ float s1s[NS], bbs[NS];     // S1_n, B_n
  __shared__ float ysum[NS*DD];
  __shared__ float csum[NS], dsum[NS];
  int bt = blockIdx.x, q4 = blockIdx.y;
  int t = threadIdx.x, wid = t >> 5, lane = t & 31;
  const float* qtb = qt + (size_t)bt*NS*DD;
  for (int i = t; i < 4*DD; i += 512) {
    int m = i / DD, c = i - m*DD;
    float gc = g[c];
    qgp[m*DD + c] = pack2(gc*qtb[(2*m)*DD + c], gc*qtb[(2*m+1)*DD + c]);
  }
  if (wid < 8) {                 // warp n computes S1_n, B_n
    int n = wid;
    float s1 = 0.f, bbv = 0.f;
#pragma unroll
    for (int j = 0; j < 6; j++) {
      int c = j*32 + lane;
      float qv = qtb[n*DD + c];
      s1 += g[c]*qv; bbv += b[c]*qv;
    }
#pragma unroll
    for (int o = 16; o; o >>= 1) {
      s1  += __shfl_xor_sync(0xffffffffu, s1,  o);
      bbv += __shfl_xor_sync(0xffffffffu, bbv, o);
    }
    if (lane == 0) { s1s[n] = s1; bbs[n] = bbv; }
  }
  for (int i = t; i < NS*DD; i += 512) ysum[i] = 0.f;
  if (t < NS) { csum[t] = 0.f; dsum[t] = 0.f; }
  __syncthreads();

  ull s1p[4], bp[4];
#pragma unroll
  for (int m = 0; m < 4; m++) {
    s1p[m] = pack2(s1s[2*m], s1s[2*m+1]);
    bp[m]  = pack2(bbs[2*m], bbs[2*m+1]);
  }

  ull yacc[4][6] = {};
  ull dacc[4] = {};   // packed softmax-weight sums (den)
  ull cacc[4] = {};   // packed sum of w*inv*mean

  const float* fb = features + (size_t)bt * LL * DD;
  int s_begin = q4*256 + wid;
  int s_end   = q4*256 + 256;
  float vn[6];
  {
    const float* xr = fb + (size_t)s_begin * DD;
#pragma unroll
    for (int j = 0; j < 6; j++) vn[j] = xr[j*32 + lane];
  }
  for (int s = s_begin; s < s_end; s += 16) {
    float v[6];
#pragma unroll
    for (int j = 0; j < 6; j++) v[j] = vn[j];
    int s2i = s + 16;
    if (s2i < s_end) {
      const float* xr = fb + (size_t)s2i * DD;
#pragma unroll
      for (int j = 0; j < 6; j++) vn[j] = xr[j*32 + lane];
    }
    // moments + raw dots, ALL reduced in one shuffle round
    float sm = 0.f, sq = 0.f;
#pragma unroll
    for (int j = 0; j < 6; j++) { sm += v[j]; sq += v[j]*v[j]; }
    ull msq = pack2(sm, sq);
    ull dd[4] = {};
#pragma unroll
    for (int mI = 0; mI < 4; mI++) {
#pragma unroll
      for (int j = 0; j < 6; j++)
        ffma2(dd[mI], dup2(v[j]), qgp[mI*DD + j*32 + lane]);
    }
#pragma unroll
    for (int o = 16; o; o >>= 1) {
      msq = add2(msq, __shfl_xor_sync(0xffffffffu, msq, o));
#pragma unroll
      for (int mI = 0; mI < 4; mI++)
        dd[mI] = add2(dd[mI], __shfl_xor_sync(0xffffffffu, dd[mI], o));
    }
    unpack2(msq, sm, sq);
    float mean = sm * (1.f/DD);
    float inv = rsqrtf(fmaxf(sq*(1.f/DD) - mean*mean, 0.f) + 1e-5f);
    float nim = -inv*mean;
    // p pairs
    float p[NS];
#pragma unroll
    for (int mI = 0; mI < 4; mI++) {
      ull pp = bp[mI];
      ffma2(pp, dd[mI], dup2(inv));
      ffma2(pp, s1p[mI], dup2(nim));
      unpack2(pp, p[2*mI], p[2*mI+1]);
    }
    // softmax over 8 slots (local)
    float mx = p[0];
#pragma unroll
    for (int n = 1; n < NS; n++) mx = fmaxf(mx, p[n]);
    float ssum = 0.f;
#pragma unroll
    for (int n = 0; n < NS; n++) { p[n] = __expf(p[n]-mx); ssum += p[n]; }
    float r = 1.f / ssum;
#pragma unroll
    for (int mI = 0; mI < 4; mI++) {
      ull w2 = pack2(p[2*mI]*r, p[2*mI+1]*r);
      dacc[mI] = add2(dacc[mI], w2);
      ull wiv = mul2(w2, dup2(inv));
      ffma2(cacc[mI], wiv, dup2(mean));
#pragma unroll
      for (int j = 0; j < 6; j++) ffma2(yacc[mI][j], dup2(v[j]), wiv);
    }
  }
  // merge across warps
#pragma unroll
  for (int mI = 0; mI < 4; mI++) {
#pragma unroll
    for (int j = 0; j < 6; j++) {
      float lo, hi; unpack2(yacc[mI][j], lo, hi);
      atomicAdd(&ysum[(2*mI)*DD + j*32 + lane], lo);
      atomicAdd(&ysum[(2*mI+1)*DD + j*32 + lane], hi);
    }
  }
  if (lane == 0) {
#pragma unroll
    for (int mI = 0; mI < 4; mI++) {
      float lo, hi;
      unpack2(dacc[mI], lo, hi);
      atomicAdd(&dsum[2*mI], lo); atomicAdd(&dsum[2*mI+1], hi);
      unpack2(cacc[mI], lo, hi);
      atomicAdd(&csum[2*mI], lo); atomicAdd(&csum[2*mI+1], hi);
    }
  }
  __syncthreads();
  // apply deferred transform on the partial (linear in partials)
  float* yp = y + (size_t)q4 * ROWS_S * DD + (size_t)bt*NS*DD;
  for (int i = t; i < NS*DD; i += 512) {
    int n = i / DD, d = i - n*DD;
    yp[i] = g[d]*(ysum[i] - csum[n]) + b[d]*dsum[n];
  }
  if (t < NS) den[q4*ROWS_S + bt*NS + t] = dsum[t];
}

// ---------------- small-tile GEMM: C = alpha*((sum_p A_p)/sum_p rowdiv_p) @ W^T [+bias][relu][+res] ----------------
__global__ __launch_bounds__(256)
void gemm_s(const float* __restrict__ A, const float* __restrict__ W,
            const float* __restrict__ bias, const float* __restrict__ res,
            const float* __restrict__ rowdiv,
            float* __restrict__ C, int M, int Ncols, int K, int ldc,
            float alpha, int relu, int nacc) {
  __shared__ __align__(16) float As[16][36];
  __shared__ __align__(16) float Ws[16][68];
  int t = threadIdx.x;
  int m0 = blockIdx.x * 32, n0 = blockIdx.y * 64;
  int lrA = t >> 2, lcA = (t & 3) << 2;
  int lrW = t >> 2, lcW = (t & 3) << 2;
  const float* Ap = A + (size_t)(m0 + (lrA & 31)) * K + lcA;
  const float* Wp = W + (size_t)(n0 + lrW) * K + lcW;
  float rsA = 1.f;
  if (rowdiv && t < 128) {
    float d = 0.f;
    for (int p = 0; p < nacc; p++) d += rowdiv[p*ROWS_S + m0 + lrA];
    rsA = 1.f / d;
  }
  int ty = t >> 4, tx = t & 15;
  ull acc[4] = {};

  for (int k0 = 0; k0 < K; k0 += 16) {
    float4 a0 = make_float4(0.f,0.f,0.f,0.f);
    if (t < 128) {
      a0 = *(const float4*)(Ap + k0);
      for (int p = 1; p < nacc; p++) {
        float4 a2 = *(const float4*)(Ap + (size_t)p*ROWS_S*DD + k0);
        a0.x += a2.x; a0.y += a2.y; a0.z += a2.z; a0.w += a2.w;
      }
      a0.x *= rsA; a0.y *= rsA; a0.z *= rsA; a0.w *= rsA;
    }
    float4 w0 = *(const float4*)(Wp + k0);
    __syncthreads();
    if (t < 128) {
      As[lcA+0][lrA] = a0.x; As[lcA+1][lrA] = a0.y;
      As[lcA+2][lrA] = a0.z; As[lcA+3][lrA] = a0.w;
    }
    Ws[lcW+0][lrW] = w0.x; Ws[lcW+1][lrW] = w0.y;
    Ws[lcW+2][lrW] = w0.z; Ws[lcW+3][lrW] = w0.w;
    __syncthreads();
#pragma unroll
    for (int k = 0; k < 16; k++) {
      ull ap = *(const ull*)&As[k][ty*2];
      float4 wv = *(const float4*)&Ws[k][tx*4];
      ffma2(acc[0], ap, dup2(wv.x));
      ffma2(acc[1], ap, dup2(wv.y));
      ffma2(acc[2], ap, dup2(wv.z));
      ffma2(acc[3], ap, dup2(wv.w));
    }
  }

  int m = m0 + ty*2, n = n0 + tx*4;
  float r0[4], r1[4];
#pragma unroll
  for (int j = 0; j < 4; j++) {
    float lo, hi; unpack2(acc[j], lo, hi);
    float bv = bias ? bias[n+j] : 0.f;
    float v0 = lo*alpha + bv;
    float v1 = hi*alpha + bv;
    if (relu) { v0 = fmaxf(v0, 0.f); v1 = fmaxf(v1, 0.f); }
    if (res)  { v0 += res[(size_t)m*Ncols + n+j]; v1 += res[(size_t)(m+1)*Ncols + n+j]; }
    r0[j] = v0; r1[j] = v1;
  }
  *(float4*)(C + (size_t)m*ldc + n)     = make_float4(r0[0], r0[1], r0[2], r0[3]);
  *(float4*)(C + (size_t)(m+1)*ldc + n) = make_float4(r1[0], r1[1], r1[2], r1[3]);
}

// ---------------- MHA core, query-chunked: grid (Bb*4, S/64); nh=4, hd=48 ----------------
// QK stage: each thread owns ONE query (q in 12 float4 regs), 4 threads/query.
__global__ __launch_bounds__(256)
void mha_kernel(const float* __restrict__ qkv, float* __restrict__ out, int S, int Bb) {
  extern __shared__ __align__(16) float smbuf[];
  int b = blockIdx.x >> 2, h = blockIdx.x & 3;
  int i0 = blockIdx.y * 64;
  float* qs = smbuf;
  float* ks = qs + 64*48;
  float* vs = ks + S*48;
  float* sc = vs + S*48;
  int t = threadIdx.x;
  for (int i = t; i < 64*48; i += 256) {
    int s = i / 48, e = i - s*48;
    qs[i] = qkv[((size_t)(i0+s)*Bb + b)*576 + h*48 + e];
  }
  for (int i = t; i < S*48; i += 256) {
    int s = i / 48, e = i - s*48;
    size_t ro = ((size_t)s*Bb + b)*576 + h*48 + e;
    ks[i] = qkv[ro + 192]; vs[i] = qkv[ro + 384];
  }
  __syncthreads();
  const float scale = 0.14433756729740643f;
  // QK^T: q held in registers
  {
    int iq = t >> 2, s4 = t & 3;
    float4 qreg[12];
#pragma unroll
    for (int j = 0; j < 12; j++) qreg[j] = *(const float4*)(qs + iq*48 + j*4);
    for (int s = s4; s < S; s += 4) {
      const float4* kr = (const float4*)(ks + s*48);
      ull pp = 0;
#pragma unroll
      for (int j = 0; j < 12; j++) {
        float4 kx = kr[j];
        ffma2(pp, pack2(qreg[j].x, qreg[j].y), pack2(kx.x, kx.y));
        ffma2(pp, pack2(qreg[j].z, qreg[j].w), pack2(kx.z, kx.w));
      }
      float lo, hi; unpack2(pp, lo, hi);
      sc[iq*S + s] = (lo + hi) * scale;
    }
  }
  __syncthreads();
  int warp = t >> 5, lane = t & 31;
  for (int i = warp; i < 64; i += 8) {
    float mx = -1e30f;
    for (int s = lane; s < S; s += 32) mx = fmaxf(mx, sc[i*S+s]);
#pragma unroll
    for (int o = 16; o; o >>= 1) mx = fmaxf(mx, __shfl_xor_sync(0xffffffffu, mx, o));
    float sum = 0.f;
    for (int s = lane; s < S; s += 32) { float e = __expf(sc[i*S+s]-mx); sc[i*S+s]=e; sum += e; }
#pragma unroll
    for (int o = 16; o; o >>= 1) sum += __shfl_xor_sync(0xffffffffu, sum, o);
    float r = 1.f / sum;
    for (int s = lane; s < S; s += 32) sc[i*S+s] *= r;
  }
  __syncthreads();
  // AV, float4-vectorized with packed FFMA2
  for (int idx = t; idx < 64*12; idx += 256) {
    int i = idx / 12, e4 = idx - i*12;
    ull a0 = 0, a1 = 0;
    const float* vcol = vs + e4*4;
#pragma unroll 4
    for (int s = 0; s < S; s++) {
      ull w2 = dup2(sc[i*S + s]);
      float4 vv = *(const float4*)(vcol + s*48);
      ffma2(a0, w2, pack2(vv.x, vv.y));
      ffma2(a1, w2, pack2(vv.z, vv.w));
    }
    float o0, o1, o2, o3;
    unpack2(a0, o0, o1); unpack2(a1, o2, o3);
    *(float4*)(out + ((size_t)(i0+i)*Bb + b)*192 + h*48 + e4*4) = make_float4(o0, o1, o2, o3);
  }
}

// ---------------- launcher ----------------
extern "C" void kernel_launch(void* const* d_in, const int* in_sizes, int n_in,
                              void* d_out, int out_size) {
  const float* features   = (const float*)d_in[0];
  const float* prev_slots = (const float*)d_in[1];
  const float* lnq_g  = (const float*)d_in[2],  *lnq_b  = (const float*)d_in[3];
  const float* lnkv_g = (const float*)d_in[4],  *lnkv_b = (const float*)d_in[5];
  const float* wq = (const float*)d_in[6],  *wk = (const float*)d_in[7];
  const float* wvw= (const float*)d_in[8],  *wo = (const float*)d_in[9];
  const float* lnt_g  = (const float*)d_in[10], *lnt_b  = (const float*)d_in[11];
  const float* t_in_w = (const float*)d_in[12], *t_in_b = (const float*)d_in[13];
  const float* t_out_w= (const float*)d_in[14], *t_out_b= (const float*)d_in[15];
  const float* lno_g  = (const float*)d_in[16], *lno_b  = (const float*)d_in[17];
  const float* o_in_w = (const float*)d_in[18], *o_in_b = (const float*)d_in[19];
  const float* o_out_w= (const float*)d_in[20], *o_out_b= (const float*)d_in[21];
  const float* lnp_g  = (const float*)d_in[22], *lnp_b  = (const float*)d_in[23];
  const float* w1 = (const float*)d_in[24], *b1 = (const float*)d_in[25];
  const float* w2 = (const float*)d_in[26], *b2 = (const float*)d_in[27];
  float* outp = (float*)d_out;

  float *qt, *wkq, *wvo, *y, *den, *t1, *t2, *qkvb, *hid;
  cudaGetSymbolAddress((void**)&qt,   g_qt);
  cudaGetSymbolAddress((void**)&wkq,  g_wkq);
  cudaGetSymbolAddress((void**)&wvo,  g_wvo);
  cudaGetSymbolAddress((void**)&y,    g_y);
  cudaGetSymbolAddress((void**)&den,  g_den);
  cudaGetSymbolAddress((void**)&t1,   g_t1);
  cudaGetSymbolAddress((void**)&t2,   g_t2);
  cudaGetSymbolAddress((void**)&qkvb, g_qkvb);
  cudaGetSymbolAddress((void**)&hid,  g_hid);

  cudaFuncSetAttribute(mha_kernel, cudaFuncAttributeMaxDynamicSharedMemorySize, 98304);

  const float isq = 0.07216878364870323f;   // 1/sqrt(192)

  // (1) Wkq = wk^T @ wq
  mm192_kernel<<<dim3(6, 3), 256>>>(wk, wq, wkq, 1);
  // (2) qt = isq * LN(prev_slots;lnq) @ Wkq^T
  gemm_ln<<<dim3(32, 3), 256>>>(prev_slots, wkq, nullptr, lnq_g, lnq_b,
                                qt, DD, isq, 0, 0);
  // (3) Wvo = wo @ wv
  mm192_kernel<<<dim3(6, 3), 256>>>(wo, wvw, wvo, 0);
  // (4) fused LN + inverse cross-attention stream (4 key-slices per bt)
  psb_stream_kernel<<<dim3(BT, NPART), 512>>>(features, qt, lnkv_g, lnkv_b, y, den);
  // (5) t1 = (sum_p y_p / sum_p den_p) @ Wvo^T
  gemm_s<<<dim3(32, 3), 256>>>(y, wvo, nullptr, nullptr, den,
                               t1, ROWS_S, DD, DD, DD, 1.f, 0, NPART);
  // (6-8) time attention
  gemm_ln<<<dim3(32, 9), 256>>>(t1, t_in_w, t_in_b, lnt_g, lnt_b,
                                qkvb, 576, 1.f, 0, 0);
  mha_kernel<<<dim3(32, 2), 256, (64*48 + 2*128*48 + 64*128)*4>>>(qkvb, t1, 128, 8);
  gemm_s<<<dim3(32, 3), 256>>>(t1, t_out_w, t_out_b, nullptr, nullptr,
                               t2, ROWS_S, DD, DD, DD, 1.f, 0, 1);
  // (9-11) object attention (perm fused into LN+GEMM)
  gemm_ln<<<dim3(32, 9), 256>>>(t2, o_in_w, o_in_b, lno_g, lno_b,
                                qkvb, 576, 1.f, 0, 1);
  mha_kernel<<<dim3(64, 1), 256, (64*48 + 2*64*48 + 64*64)*4>>>(qkvb, t1, 64, 16);
  gemm_s<<<dim3(32, 3), 256>>>(t1, o_out_w, o_out_b, nullptr, nullptr,
                               t2, ROWS_S, DD, DD, DD, 1.f, 0, 1);
  // (12-13) fused LN+FFN(relu) -> proj + residual(prev_slots)
  gemm_ln<<<dim3(32, 8), 256>>>(t2, w1, b1, lnp_g, lnp_b,
                                hid, 512, 1.f, 1, 0);
  gemm_s<<<dim3(32, 3), 256>>>(hid, w2, b2, prev_slots, nullptr,
                               outp, ROWS_S, DD, 512, DD, 1.f, 0, 1);
}